// round 13
// baseline (speedup 1.0000x reference)
#include <cuda_runtime.h>
#include <cuda_fp16.h>
#include <math.h>
#include <stdint.h>

typedef __half h16;
#define TT 1024
#define SCALE_QK 0.07216878364870323f

// ------------------------- device scratch (no cudaMalloc) -------------------
__device__ float g_qkv  [2048*2112];   // qlow | kv | k_pe(fp32, pre-rope)
__device__ float g_mb   [2048];

__device__ h16 g_xh[2048*4096];
__device__ h16 g_qlow[2048*1536];
__device__ h16 g_q[2048*6144];
__device__ h16 g_kv[2048*512];
__device__ h16 g_kvexp[2048ll*8192];
__device__ h16 g_kpe[2048*64];
__device__ h16 g_at[2048*4096];
__device__ h16 g_wab[2112*4096];
__device__ h16 g_wqb[6144*1536];
__device__ h16 g_wkvb[8192*512];
__device__ h16 g_wo[4096*4096];

// ------------------------------ PTX helpers (sm_80-safe) --------------------
__device__ __forceinline__ uint32_t smem_u32(const void* p) {
    uint32_t a;
    asm("{ .reg .u64 t; cvta.to.shared.u64 t, %1; cvt.u32.u64 %0, t; }"
        : "=r"(a) : "l"(p));
    return a;
}

#define LDSM4(r, a) asm volatile( \
    "ldmatrix.sync.aligned.m8n8.x4.shared.b16 {%0,%1,%2,%3}, [%4];" \
    : "=r"((r)[0]), "=r"((r)[1]), "=r"((r)[2]), "=r"((r)[3]) : "r"(a))

#define LDSM4T(r, a) asm volatile( \
    "ldmatrix.sync.aligned.m8n8.x4.trans.shared.b16 {%0,%1,%2,%3}, [%4];" \
    : "=r"((r)[0]), "=r"((r)[1]), "=r"((r)[2]), "=r"((r)[3]) : "r"(a))

#define MMAH(d, a, b0, b1) asm volatile( \
    "mma.sync.aligned.m16n8k16.row.col.f32.f16.f16.f32 " \
    "{%0,%1,%2,%3},{%4,%5,%6,%7},{%8,%9},{%0,%1,%2,%3};" \
    : "+f"((d)[0]), "+f"((d)[1]), "+f"((d)[2]), "+f"((d)[3]) \
    : "r"((a)[0]), "r"((a)[1]), "r"((a)[2]), "r"((a)[3]), "r"(b0), "r"(b1))

#define MMAH_P(d, a0, a1, a2, a3, b0, b1) asm volatile( \
    "mma.sync.aligned.m16n8k16.row.col.f32.f16.f16.f32 " \
    "{%0,%1,%2,%3},{%4,%5,%6,%7},{%8,%9},{%0,%1,%2,%3};" \
    : "+f"((d)[0]), "+f"((d)[1]), "+f"((d)[2]), "+f"((d)[3]) \
    : "r"(a0), "r"(a1), "r"(a2), "r"(a3), "r"(b0), "r"(b1))

__device__ __forceinline__ void cpa16(uint32_t dst, const void* src, int valid) {
    int sz = valid ? 16 : 0;
    asm volatile("cp.async.cg.shared.global [%0], [%1], 16, %2;"
                 :: "r"(dst), "l"(src), "r"(sz));
}
#define CP_COMMIT() asm volatile("cp.async.commit_group;" ::: "memory")
#define CP_WAIT(n)  asm volatile("cp.async.wait_group %0;" :: "n"(n) : "memory")

__device__ __forceinline__ uint32_t packh(float a, float b) {
    __half2 t = __floats2half2_rn(a, b);
    return *reinterpret_cast<uint32_t*>(&t);
}

// Load one 128x32 h16 plane into swizzled smem (rows of 64B).
__device__ __forceinline__ void load_plane(uint32_t sb, const h16* __restrict__ G,
                                           int row0, int ld, int k0, int tid,
                                           int nvalid) {
#pragma unroll
    for (int i = 0; i < 2; i++) {
        int idx = tid * 2 + i;
        int r = idx >> 2, c = idx & 3;
        uint32_t dst = sb + r * 64 + ((c ^ ((r >> 1) & 3)) << 4);
        int ok = r < nvalid;
        const h16* src = G + (size_t)(row0 + (ok ? r : 0)) * ld + k0 + c * 8;
        cpa16(dst, src, ok);
    }
}

// Load one 64x32 h16 subplane (256 threads -> 1 line each). G pre-offset.
__device__ __forceinline__ void load_plane64(uint32_t sb, const h16* __restrict__ G,
                                             int ld, int tid) {
    int r = tid >> 2, c = tid & 3;
    uint32_t dst = sb + r * 64 + ((c ^ ((r >> 1) & 3)) << 4);
    cpa16(dst, G + (size_t)r * ld + c * 8, 1);
}

// Load one 64x128 h16 V plane (rows of 256B) with row-xor swizzle; row stride ld.
__device__ __forceinline__ void load_v(uint32_t sb, const h16* __restrict__ G,
                                       int ld, int tid) {
#pragma unroll
    for (int i = 0; i < 4; i++) {
        int idx = i * 256 + tid;
        int r = idx >> 4, c = idx & 15;
        uint32_t dst = sb + r * 256 + ((c ^ (r & 7)) << 4);
        cpa16(dst, G + (size_t)r * ld + c * 8, 1);
    }
}

// ---------------------------------------------------------------------------
// Single-pass fp16 HMMA GEMM body, k-chunk 64 (two 32-k subplanes/stage),
// 3-stage cp.async pipeline (32KB/stage). H16OUT=0: fp32 C; 1: fp16 C.
// ---------------------------------------------------------------------------
#define GEMM_SMEM 98304
template<int H16OUT>
__device__ __forceinline__ void gemm_body(
    const h16* __restrict__ A, const h16* __restrict__ B,
    float* __restrict__ C, h16* __restrict__ Ch,
    int N, int K, int lda, int ldb, int ldc, int m0, int n0, char* smem)
{
    int tid = threadIdx.x, lane = tid & 31, wid = tid >> 5;
    int mw = (wid & 1) * 64, nw = (wid >> 1) * 32;
    uint32_t s0 = smem_u32(smem);
    int nvB = min(128, N - n0);
    int nch = K >> 6;

    uint32_t rowA[4]; int sA[4];
#pragma unroll
    for (int mt = 0; mt < 4; mt++) {
        int r = mw + mt * 16 + (lane & 15);
        rowA[mt] = r * 64; sA[mt] = (r >> 1) & 3;
    }
    uint32_t rowB[2]; int sB[2];
#pragma unroll
    for (int h2 = 0; h2 < 2; h2++) {
        int r = nw + h2 * 16 + (lane & 7) + ((lane >> 4) << 3);
        rowB[h2] = r * 64; sB[h2] = (r >> 1) & 3;
    }
    int aCk = (lane >> 4) & 1, bCk = (lane >> 3) & 1;

    float acc[4][4][4];
#pragma unroll
    for (int i = 0; i < 4; i++)
#pragma unroll
        for (int j = 0; j < 4; j++)
#pragma unroll
            for (int r = 0; r < 4; r++) acc[i][j][r] = 0.f;

    // prologue: stages 0,1
#pragma unroll
    for (int pc = 0; pc < 2; pc++) {
        if (pc < nch) {
            uint32_t sb = s0 + pc * 32768;
            int k0 = pc * 64;
            load_plane(sb,         A, m0, lda, k0,      tid, 128);
            load_plane(sb + 8192,  A, m0, lda, k0 + 32, tid, 128);
            load_plane(sb + 16384, B, n0, ldb, k0,      tid, nvB);
            load_plane(sb + 24576, B, n0, ldb, k0 + 32, tid, nvB);
        }
        CP_COMMIT();
    }

    for (int c = 0; c < nch; c++) {
        CP_WAIT(1);
        __syncthreads();
        if (c + 2 < nch) {
            uint32_t sb = s0 + ((c + 2) % 3) * 32768;
            int k0 = (c + 2) * 64;
            load_plane(sb,         A, m0, lda, k0,      tid, 128);
            load_plane(sb + 8192,  A, m0, lda, k0 + 32, tid, 128);
            load_plane(sb + 16384, B, n0, ldb, k0,      tid, nvB);
            load_plane(sb + 24576, B, n0, ldb, k0 + 32, tid, nvB);
        }
        CP_COMMIT();

        uint32_t base = s0 + (c % 3) * 32768;
#pragma unroll
        for (int ks = 0; ks < 4; ks++) {
            uint32_t pA = base + (ks >> 1) * 8192;
            uint32_t pB = base + 16384 + (ks >> 1) * 8192;
            int cA = ((ks & 1) << 1) + aCk, cB = ((ks & 1) << 1) + bCk;
            uint32_t af[4][4], bf[2][4];
#pragma unroll
            for (int mt = 0; mt < 4; mt++)
                LDSM4(af[mt], pA + rowA[mt] + (uint32_t)((cA ^ sA[mt]) << 4));
#pragma unroll
            for (int h2 = 0; h2 < 2; h2++)
                LDSM4(bf[h2], pB + rowB[h2] + (uint32_t)((cB ^ sB[h2]) << 4));
#pragma unroll
            for (int mt = 0; mt < 4; mt++)
#pragma unroll
                for (int nt = 0; nt < 4; nt++)
                    MMAH(acc[mt][nt], af[mt],
                         bf[nt >> 1][(nt & 1) * 2], bf[nt >> 1][(nt & 1) * 2 + 1]);
        }
    }

#pragma unroll
    for (int mt = 0; mt < 4; mt++) {
        int r0 = m0 + mw + mt * 16 + (lane >> 2);
#pragma unroll
        for (int nt = 0; nt < 4; nt++) {
            int col = n0 + nw + nt * 8 + 2 * (lane & 3);
            if (col < N) {
                if (H16OUT == 0) {
                    float2 v0 = make_float2(acc[mt][nt][0], acc[mt][nt][1]);
                    float2 v1 = make_float2(acc[mt][nt][2], acc[mt][nt][3]);
                    *(float2*)(C + (size_t)r0 * ldc + col) = v0;
                    *(float2*)(C + (size_t)(r0 + 8) * ldc + col) = v1;
                } else {
                    *(uint32_t*)(Ch + (size_t)r0 * ldc + col) =
                        packh(acc[mt][nt][0], acc[mt][nt][1]);
                    *(uint32_t*)(Ch + (size_t)(r0 + 8) * ldc + col) =
                        packh(acc[mt][nt][2], acc[mt][nt][3]);
                }
            }
        }
    }
}

// fp32-out GEMM
__global__ void __launch_bounds__(256, 2) gemm1_k(
    const h16* __restrict__ A, const h16* __restrict__ B, float* __restrict__ C,
    int N, int K, int lda, int ldb, int ldc)
{
    extern __shared__ char smem[];
    gemm_body<0>(A, B, C, nullptr, N, K, lda, ldb, ldc,
                 blockIdx.y * 128, blockIdx.x * 128, smem);
}

// dual fp16-out GEMM (q up-proj + kv up-proj)
__global__ void __launch_bounds__(256, 2) gemm1h_dual_k(
    const h16* __restrict__ A0, const h16* __restrict__ B0, h16* __restrict__ C0,
    int N0, int K0, int lda0, int ldb0, int ldc0,
    const h16* __restrict__ A1, const h16* __restrict__ B1, h16* __restrict__ C1,
    int N1, int K1, int lda1, int ldb1, int ldc1, int nx0)
{
    extern __shared__ char smem[];
    if ((int)blockIdx.x < nx0)
        gemm_body<1>(A0, B0, nullptr, C0, N0, K0, lda0, ldb0, ldc0,
                     blockIdx.y * 128, blockIdx.x * 128, smem);
    else
        gemm_body<1>(A1, B1, nullptr, C1, N1, K1, lda1, ldb1, ldc1,
                     blockIdx.y * 128, (blockIdx.x - nx0) * 128, smem);
}

// ---------------------------------------------------------------------------
// Fused flash attention, single fp16 planes. 112KB smem -> 2 CTAs/SM.
// ---------------------------------------------------------------------------
#define FL_SMEM 114688
__global__ void __launch_bounds__(256, 2) flash_k(
    const h16* __restrict__ q_, const h16* __restrict__ kv_,
    const h16* __restrict__ kpe_,
    const float* __restrict__ mb, const int* __restrict__ pos,
    h16* __restrict__ at_)
{
    extern __shared__ char smem[];
    int bh = blockIdx.x, b = bh >> 5, h = bh & 31;
    int qi = 7 - blockIdx.y;
    int t0 = qi * 128;
    int tid = threadIdx.x, lane = tid & 31, wid = tid >> 5;
    int wrow = wid * 16;

    uint32_t S0 = smem_u32(smem);
    uint32_t Qs = S0;                  // 49152
    uint32_t Kb = S0 + 49152;          // 2 stages x 24576
    uint32_t Vb = S0 + 98304;          // 16384

    const h16* Qg = q_ + ((size_t)(b * 1024 + t0)) * 6144 + h * 192;
    const h16* KN = kv_ + (size_t)b * 1024 * 8192 + h * 256;
    const h16* KP = kpe_ + (size_t)b * 1024 * 64;
    const h16* Vg = KN + 128;
    const float* mbb = mb + b * 1024;

#pragma unroll
    for (int sp = 0; sp < 6; sp++)
        load_plane(Qs + sp * 8192, Qg, 0, 6144, sp * 32, tid, 128);
#pragma unroll
    for (int sp = 0; sp < 4; sp++)
        load_plane64(Kb + sp * 4096, KN + sp * 32, 8192, tid);
#pragma unroll
    for (int sp = 4; sp < 6; sp++)
        load_plane64(Kb + sp * 4096, KP + (sp - 4) * 32, 64, tid);
    CP_COMMIT();

    // ---- rope Q pe columns (subplanes 4,5) in smem ----
    CP_WAIT(0);
    __syncthreads();
    {
        int j = tid & 31;
        float invf = powf(10000.f, -(float)j / 32.f);
#pragma unroll
        for (int it = 0; it < 16; it++) {
            int r = (tid >> 5) + it * 8;
            uint32_t off = (uint32_t)(r * 64 +
                (((j >> 3) ^ ((r >> 1) & 3)) << 4) + (j & 7) * 2);
            h16* q4 = (h16*)(smem + 4 * 8192 + off);
            h16* q5 = (h16*)(smem + 5 * 8192 + off);
            float x1 = __half2float(*q4), x2 = __half2float(*q5);
            float p = (float)pos[b * 1024 + t0 + r];
            float sn, cs; sincosf(p * invf, &sn, &cs);
            *q4 = __float2half_rn(x1 * cs - x2 * sn);
            *q5 = __float2half_rn(x1 * sn + x2 * cs);
        }
    }

    int nst = (t0 + 128) >> 6;
    float m0 = -1e30f, m1 = -1e30f, l0 = 0.f, l1 = 0.f;
    float O[16][4];
#pragma unroll
    for (int i = 0; i < 16; i++)
#pragma unroll
        for (int j = 0; j < 4; j++) O[i][j] = 0.f;

    int rA = wrow + (lane & 15);
    int swA = (rA >> 1) & 3;
    int rB[4], swB[4];
#pragma unroll
    for (int g = 0; g < 4; g++) {
        rB[g] = g * 16 + (lane & 7) + ((lane >> 4) << 3);
        swB[g] = (rB[g] >> 1) & 3;
    }
    int aSel = (lane >> 4) & 1, bSel = (lane >> 3) & 1;
    int trow = t0 + wrow + (lane >> 2);

    for (int i = 0; i < nst; i++) {
        __syncthreads();
        load_v(Vb, Vg + (size_t)i * 64 * 8192, 8192, tid);
        CP_COMMIT();
        if (i + 1 < nst) {
            uint32_t Ks = Kb + ((i + 1) & 1) * 24576;
            size_t roff = (size_t)(i + 1) * 64;
#pragma unroll
            for (int sp = 0; sp < 4; sp++)
                load_plane64(Ks + sp * 4096, KN + roff * 8192 + sp * 32, 8192, tid);
#pragma unroll
            for (int sp = 4; sp < 6; sp++)
                load_plane64(Ks + sp * 4096, KP + roff * 64 + (sp - 4) * 32, 64, tid);
        }
        CP_COMMIT();

        CP_WAIT(2);
        __syncthreads();

        // ---- S = QK^T ----
        float S[8][4];
#pragma unroll
        for (int nt = 0; nt < 8; nt++)
#pragma unroll
            for (int j = 0; j < 4; j++) S[nt][j] = 0.f;

        uint32_t Ks = Kb + (i & 1) * 24576;
#pragma unroll
        for (int ks = 0; ks < 12; ks++) {
            int sp = ks >> 1;
            int cA = ((ks & 1) << 1) + aSel;
            int cB = ((ks & 1) << 1) + bSel;
            uint32_t ah[4], bf[4][4];
            LDSM4(ah, Qs + sp * 8192 + rA * 64 + (uint32_t)((cA ^ swA) << 4));
#pragma unroll
            for (int g = 0; g < 4; g++)
                LDSM4(bf[g], Ks + sp * 4096 + rB[g] * 64 + (uint32_t)((cB ^ swB[g]) << 4));
#pragma unroll
            for (int g = 0; g < 4; g++) {
                MMAH(S[2 * g], ah, bf[g][0], bf[g][1]);
                MMAH(S[2 * g + 1], ah, bf[g][2], bf[g][3]);
            }
        }

        // ---- online softmax ----
        int s0i = i * 64;
        float mx0 = -1e30f, mx1 = -1e30f;
#pragma unroll
        for (int nt = 0; nt < 8; nt++) {
            int sb0 = s0i + nt * 8 + ((lane & 3) << 1);
            float bias0 = mbb[sb0], bias1 = mbb[sb0 + 1];
            float v0 = S[nt][0] * SCALE_QK + bias0; if (sb0     > trow)     v0 = -1e30f;
            float v1 = S[nt][1] * SCALE_QK + bias1; if (sb0 + 1 > trow)     v1 = -1e30f;
            float v2 = S[nt][2] * SCALE_QK + bias0; if (sb0     > trow + 8) v2 = -1e30f;
            float v3 = S[nt][3] * SCALE_QK + bias1; if (sb0 + 1 > trow + 8) v3 = -1e30f;
            S[nt][0] = v0; S[nt][1] = v1; S[nt][2] = v2; S[nt][3] = v3;
            mx0 = fmaxf(mx0, fmaxf(v0, v1));
            mx1 = fmaxf(mx1, fmaxf(v2, v3));
        }
        mx0 = fmaxf(mx0, __shfl_xor_sync(0xffffffffu, mx0, 1));
        mx0 = fmaxf(mx0, __shfl_xor_sync(0xffffffffu, mx0, 2));
        mx1 = fmaxf(mx1, __shfl_xor_sync(0xffffffffu, mx1, 1));
        mx1 = fmaxf(mx1, __shfl_xor_sync(0xffffffffu, mx1, 2));
        float mn0 = fmaxf(m0, mx0), mn1 = fmaxf(m1, mx1);
        float cr0 = __expf(m0 - mn0), cr1 = __expf(m1 - mn1);
        float sum0 = 0.f, sum1 = 0.f;
#pragma unroll
        for (int nt = 0; nt < 8; nt++) {
            S[nt][0] = __expf(S[nt][0] - mn0);
            S[nt][1] = __expf(S[nt][1] - mn0);
            S[nt][2] = __expf(S[nt][2] - mn1);
            S[nt][3] = __expf(S[nt][3] - mn1);
            sum0 += S[nt][0] + S[nt][1];
            sum1 += S[nt][2] + S[nt][3];
        }
        sum0 += __shfl_xor_sync(0xffffffffu, sum0, 1);
        sum0 += __shfl_xor_sync(0xffffffffu, sum0, 2);
        sum1 += __shfl_xor_sync(0xffffffffu, sum1, 1);
        sum1 += __shfl_xor_sync(0xffffffffu, sum1, 2);
        l0 = l0 * cr0 + sum0;  l1 = l1 * cr1 + sum1;
        m0 = mn0;  m1 = mn1;
#pragma unroll
        for (int nd = 0; nd < 16; nd++) {
            O[nd][0] *= cr0; O[nd][1] *= cr0;
            O[nd][2] *= cr1; O[nd][3] *= cr1;
        }

        CP_WAIT(1);
        __syncthreads();

        // ---- O += P @ V ----
        int rV = (lane & 15);
#pragma unroll
        for (int kc = 0; kc < 4; kc++) {
            uint32_t phi[4];
#pragma unroll
            for (int j = 0; j < 2; j++) {
                int nt = 2 * kc + j;
                phi[2 * j]     = packh(S[nt][0], S[nt][1]);
                phi[2 * j + 1] = packh(S[nt][2], S[nt][3]);
            }
            int row = kc * 16 + rV;
            int sw = row & 7;
            uint32_t rbase = (uint32_t)row * 256;
            int cgrp = (lane >> 4) << 3;
#pragma unroll
            for (int g = 0; g < 8; g++) {
                int cch = (((g << 4) + cgrp) >> 3) ^ sw;
                uint32_t v4[4];
                LDSM4T(v4, Vb + rbase + (uint32_t)(cch << 4));
                MMAH_P(O[2 * g],     phi[0], phi[1], phi[2], phi[3], v4[0], v4[1]);
                MMAH_P(O[2 * g + 1], phi[0], phi[1], phi[2], phi[3], v4[2], v4[3]);
            }
        }
    }

    // ---- epilogue: O / l -> fp16 plane ----
    float inv0 = 1.f / l0, inv1 = 1.f / l1;
    size_t row0 = ((size_t)(b * 1024) + trow) * 4096 + h * 128;
    size_t row1 = row0 + (size_t)8 * 4096;
    int dcol = (lane & 3) * 2;
#pragma unroll
    for (int nd = 0; nd < 16; nd++) {
        int c = nd * 8 + dcol;
        *(uint32_t*)(at_ + row0 + c) = packh(O[nd][0] * inv0, O[nd][1] * inv0);
        *(uint32_t*)(at_ + row1 + c) = packh(O[nd][2] * inv1, O[nd][3] * inv1);
    }
}

// ------------------------- conversion / elementwise -------------------------
// prep_small: wab transpose+convert + x fp16 convert (critical path).
__global__ void prep_small_k(const float* __restrict__ wq_a,
                             const float* __restrict__ wkv_a,
                             const float* __restrict__ x,
                             h16* __restrict__ wab, h16* __restrict__ xh)
{
    __shared__ float t[32][33];
    int bx = blockIdx.x;
    int tx = threadIdx.x, ty = threadIdx.y;
    if (bx >= 8448) {            // x convert: 32768 blocks
        long i = (long)(bx - 8448) * 256 + ty * 32 + tx;
        xh[i] = __float2half_rn(x[i]);
        return;
    }
    const float* W; int K, N, nx, tIdx, rowOff;
    if (bx < 6144) { W = wq_a;  K = 4096; N = 1536; nx = 48; tIdx = bx;        rowOff = 0; }
    else           { W = wkv_a; K = 4096; N = 576;  nx = 18; tIdx = bx - 6144; rowOff = 1536; }
    int n0 = (tIdx % nx) * 32, k0 = (tIdx / nx) * 32;
#pragma unroll
    for (int j = 0; j < 32; j += 8)
        t[ty + j][tx] = W[(size_t)(k0 + ty + j) * N + n0 + tx];
    __syncthreads();
#pragma unroll
    for (int j = 0; j < 32; j += 8)
        wab[(size_t)(rowOff + n0 + ty + j) * K + k0 + tx] =
            __float2half_rn(t[tx][ty + j]);
}

// prep_big: wqb / wkvb / wo transpose+convert (overlapped branch).
__global__ void prep_big_k(const float* __restrict__ wq_b,
                           const float* __restrict__ wkv_b,
                           const float* __restrict__ wo,
                           h16* __restrict__ wqb, h16* __restrict__ wkvb,
                           h16* __restrict__ wot)
{
    __shared__ float t[32][33];
    int bx = blockIdx.x;
    int tx = threadIdx.x, ty = threadIdx.y;
    const float* W; h16* T; int K, N, nx, tIdx;
    if (bx < 9216)       { W = wq_b;  T = wqb;  K = 1536; N = 6144; nx = 192; tIdx = bx; }
    else if (bx < 13312) { W = wkv_b; T = wkvb; K = 512;  N = 8192; nx = 256; tIdx = bx - 9216; }
    else                 { W = wo;    T = wot;  K = 4096; N = 4096; nx = 128; tIdx = bx - 13312; }
    int n0 = (tIdx % nx) * 32, k0 = (tIdx / nx) * 32;
#pragma unroll
    for (int j = 0; j < 32; j += 8)
        t[ty + j][tx] = W[(size_t)(k0 + ty + j) * N + n0 + tx];
    __syncthreads();
#pragma unroll
    for (int j = 0; j < 32; j += 8)
        T[(size_t)(n0 + ty + j) * K + k0 + tx] = __float2half_rn(t[tx][ty + j]);
}

// Fused post-down-proj: rmsnorms -> fp16, rope k_pe -> plane, mask bias.
__global__ void postdown_k(const float* __restrict__ qkv,
                           const float* __restrict__ qw,
                           const float* __restrict__ kvw,
                           const int* __restrict__ amask,
                           const int* __restrict__ pos,
                           h16* __restrict__ qlow, h16* __restrict__ kv,
                           h16* __restrict__ kpe, float* __restrict__ mb)
{
    int rb = blockIdx.x;
    int tid = threadIdx.x;
    if (rb >= 4352) {                       // mask bias: 8 blocks
        int i = (rb - 4352) * 256 + tid;
        if (i < 2048) mb[i] = amask[i] ? 0.f : -1e30f;
        return;
    }
    if (rb >= 4096) {                       // rope k_pe: 256 blocks x 8 warps
        int w = (rb - 4096) * 8 + (tid >> 5);
        int lane = tid & 31;
        const float* base = qkv + (size_t)w * 2112 + 2048;
        float p = (float)pos[w];
        float invf = powf(10000.f, -(float)lane / 32.f);
        float sn, cs; sincosf(p * invf, &sn, &cs);
        float x1 = base[lane], x2 = base[32 + lane];
        size_t ob = (size_t)w * 64;
        kpe[ob + lane]      = __float2half_rn(x1 * cs - x2 * sn);
        kpe[ob + 32 + lane] = __float2half_rn(x1 * sn + x2 * cs);
        return;
    }
    __shared__ float red[256];
    int isq = rb < 2048;
    long row = isq ? rb : rb - 2048;
    int n = isq ? 1536 : 512;
    const float* p = qkv + row * 2112 + (isq ? 0 : 1536);
    const float* w = isq ? qw : kvw;
    h16* oh = (isq ? qlow : kv) + row * n;
    float ss = 0.f;
    for (int c = tid; c < n; c += 256) { float v = p[c]; ss += v * v; }
    red[tid] = ss; __syncthreads();
    for (int s = 128; s > 0; s >>= 1) {
        if (tid < s) red[tid] += red[tid + s];
        __syncthreads();
    }
    float r = rsqrtf(red[0] / (float)n + 1e-6f);
    for (int c = tid; c < n; c += 256)
        oh[c] = __float2half_rn(p[c] * r * w[c]);
}

// ---------------------------------------------------------------------------
extern "C" void kernel_launch(void* const* d_in, const int* in_sizes, int n_in,
                              void* d_out, int out_size)
{
    const float* x        = (const float*)d_in[0];
    const float* wq_a     = (const float*)d_in[1];
    const float* q_norm_w = (const float*)d_in[2];
    const float* wq_b     = (const float*)d_in[3];
    const float* wkv_a    = (const float*)d_in[4];
    const float* kv_norm_w= (const float*)d_in[5];
    const float* wkv_b    = (const float*)d_in[6];
    const float* wo       = (const float*)d_in[7];
    const int*   amask    = (const int*)d_in[8];
    const int*   pos      = (const int*)d_in[9];
    float*       out      = (float*)d_out;

    cudaFuncSetAttribute(gemm1_k, cudaFuncAttributeMaxDynamicSharedMemorySize,
                         GEMM_SMEM);
    cudaFuncSetAttribute(gemm1h_dual_k, cudaFuncAttributeMaxDynamicSharedMemorySize,
                         GEMM_SMEM);
    cudaFuncSetAttribute(flash_k, cudaFuncAttributeMaxDynamicSharedMemorySize,
                         FL_SMEM);

    float *qkv, *mb;
    h16 *xh,*qlow,*q,*kv,*kvexp,*kpe,*at;
    h16 *wab,*wqb,*wkvb,*wot;
    cudaGetSymbolAddress((void**)&qkv,  g_qkv);
    cudaGetSymbolAddress((void**)&mb,   g_mb);
    cudaGetSymbolAddress((void**)&xh,   g_xh);
    cudaGetSymbolAddress((void**)&qlow, g_qlow);
    cudaGetSymbolAddress((void**)&q,    g_q);
    cudaGetSymbolAddress((void**)&kv,   g_kv);
    cudaGetSymbolAddress((void**)&kvexp,g_kvexp);
    cudaGetSymbolAddress((void**)&kpe,  g_kpe);
    cudaGetSymbolAddress((void**)&at,   g_at);
    cudaGetSymbolAddress((void**)&wab,  g_wab);
    cudaGetSymbolAddress((void**)&wqb,  g_wqb);
    cudaGetSymbolAddress((void**)&wkvb, g_wkvb);
    cudaGetSymbolAddress((void**)&wot,  g_wo);

    // Side stream + events, created once on the (uncaptured) correctness call.
    static cudaStream_t s2 = nullptr;
    static cudaEvent_t e0 = nullptr, e1 = nullptr;
    if (!s2) {
        cudaStreamCreateWithFlags(&s2, cudaStreamNonBlocking);
        cudaEventCreateWithFlags(&e0, cudaEventDisableTiming);
        cudaEventCreateWithFlags(&e1, cudaEventDisableTiming);
    }

    dim3 tb(32, 8);
    // fork: big weight conversions run on side branch, overlapped with
    // the down-proj chain (which only needs wab + xh).
    cudaEventRecord(e0, 0);
    cudaStreamWaitEvent(s2, e0, 0);
    prep_big_k<<<29696, tb, 0, s2>>>(wq_b, wkv_b, wo, wqb, wkvb, wot);
    cudaEventRecord(e1, s2);

    // main chain
    prep_small_k<<<41216, tb>>>(wq_a, wkv_a, x, wab, xh);
    gemm1_k<<<dim3(17, 16), 256, GEMM_SMEM>>>(xh, wab, qkv,
        2112, 4096, 4096, 4096, 2112);
    postdown_k<<<4360, 256>>>(qkv, q_norm_w, kv_norm_w, amask, pos,
                              qlow, kv, kpe, mb);
    cudaStreamWaitEvent(0, e1, 0);          // join: need wqb/wkvb (wo too)
    gemm1h_dual_k<<<dim3(112, 16), 256, GEMM_SMEM>>>(
        qlow, wqb, q,      6144, 1536, 1536, 1536, 6144,
        kv,   wkvb, kvexp, 8192, 512, 512, 512, 8192, 48);
    flash_k<<<dim3(64, 8), 256, FL_SMEM>>>(q, kvexp, kpe, mb, pos, at);
    gemm1_k<<<dim3(32, 16), 256, GEMM_SMEM>>>(at, wot, out,
        4096, 4096, 4096, 4096, 4096);
}

// round 14
// speedup vs baseline: 1.0011x; 1.0011x over previous
#include <cuda_runtime.h>
#include <cuda_fp16.h>
#include <math.h>
#include <stdint.h>

typedef __half h16;
#define TT 1024
#define SCALE_QK 0.07216878364870323f

// ------------------------- device scratch (no cudaMalloc) -------------------
__device__ float g_qkv  [2048*2112];   // qlow | kv | k_pe(fp32, pre-rope)
__device__ float g_mb   [2048];

__device__ h16 g_xh[2048*4096];
__device__ h16 g_qlow[2048*1536];
__device__ h16 g_q[2048*6144];
__device__ h16 g_kv[2048*512];
__device__ h16 g_kvexp[2048ll*8192];
__device__ h16 g_kpe[2048*64];
__device__ h16 g_at[2048*4096];
__device__ h16 g_wab[2112*4096];
__device__ h16 g_wqb[6144*1536];
__device__ h16 g_wkvb[8192*512];
__device__ h16 g_wo[4096*4096];

// ------------------------------ PTX helpers (sm_80-safe) --------------------
__device__ __forceinline__ uint32_t smem_u32(const void* p) {
    uint32_t a;
    asm("{ .reg .u64 t; cvta.to.shared.u64 t, %1; cvt.u32.u64 %0, t; }"
        : "=r"(a) : "l"(p));
    return a;
}

#define LDSM4(r, a) asm volatile( \
    "ldmatrix.sync.aligned.m8n8.x4.shared.b16 {%0,%1,%2,%3}, [%4];" \
    : "=r"((r)[0]), "=r"((r)[1]), "=r"((r)[2]), "=r"((r)[3]) : "r"(a))

#define LDSM4T(r, a) asm volatile( \
    "ldmatrix.sync.aligned.m8n8.x4.trans.shared.b16 {%0,%1,%2,%3}, [%4];" \
    : "=r"((r)[0]), "=r"((r)[1]), "=r"((r)[2]), "=r"((r)[3]) : "r"(a))

#define MMAH(d, a, b0, b1) asm volatile( \
    "mma.sync.aligned.m16n8k16.row.col.f32.f16.f16.f32 " \
    "{%0,%1,%2,%3},{%4,%5,%6,%7},{%8,%9},{%0,%1,%2,%3};" \
    : "+f"((d)[0]), "+f"((d)[1]), "+f"((d)[2]), "+f"((d)[3]) \
    : "r"((a)[0]), "r"((a)[1]), "r"((a)[2]), "r"((a)[3]), "r"(b0), "r"(b1))

#define MMAH_P(d, a0, a1, a2, a3, b0, b1) asm volatile( \
    "mma.sync.aligned.m16n8k16.row.col.f32.f16.f16.f32 " \
    "{%0,%1,%2,%3},{%4,%5,%6,%7},{%8,%9},{%0,%1,%2,%3};" \
    : "+f"((d)[0]), "+f"((d)[1]), "+f"((d)[2]), "+f"((d)[3]) \
    : "r"(a0), "r"(a1), "r"(a2), "r"(a3), "r"(b0), "r"(b1))

__device__ __forceinline__ void cpa16(uint32_t dst, const void* src, int valid) {
    int sz = valid ? 16 : 0;
    asm volatile("cp.async.cg.shared.global [%0], [%1], 16, %2;"
                 :: "r"(dst), "l"(src), "r"(sz));
}
#define CP_COMMIT() asm volatile("cp.async.commit_group;" ::: "memory")
#define CP_WAIT(n)  asm volatile("cp.async.wait_group %0;" :: "n"(n) : "memory")

__device__ __forceinline__ uint32_t packh(float a, float b) {
    __half2 t = __floats2half2_rn(a, b);
    return *reinterpret_cast<uint32_t*>(&t);
}

// Load one 128x32 h16 plane into swizzled smem (rows of 64B).
__device__ __forceinline__ void load_plane(uint32_t sb, const h16* __restrict__ G,
                                           int row0, int ld, int k0, int tid,
                                           int nvalid) {
#pragma unroll
    for (int i = 0; i < 2; i++) {
        int idx = tid * 2 + i;
        int r = idx >> 2, c = idx & 3;
        uint32_t dst = sb + r * 64 + ((c ^ ((r >> 1) & 3)) << 4);
        int ok = r < nvalid;
        const h16* src = G + (size_t)(row0 + (ok ? r : 0)) * ld + k0 + c * 8;
        cpa16(dst, src, ok);
    }
}

// Load one 64x32 h16 subplane (256 threads -> 1 line each). G pre-offset.
__device__ __forceinline__ void load_plane64(uint32_t sb, const h16* __restrict__ G,
                                             int ld, int tid) {
    int r = tid >> 2, c = tid & 3;
    uint32_t dst = sb + r * 64 + ((c ^ ((r >> 1) & 3)) << 4);
    cpa16(dst, G + (size_t)r * ld + c * 8, 1);
}

// Load one 64x128 h16 V plane (rows of 256B) with row-xor swizzle; row stride ld.
__device__ __forceinline__ void load_v(uint32_t sb, const h16* __restrict__ G,
                                       int ld, int tid) {
#pragma unroll
    for (int i = 0; i < 4; i++) {
        int idx = i * 256 + tid;
        int r = idx >> 4, c = idx & 15;
        uint32_t dst = sb + r * 256 + ((c ^ (r & 7)) << 4);
        cpa16(dst, G + (size_t)r * ld + c * 8, 1);
    }
}

// ---------------------------------------------------------------------------
// Single-pass fp16 HMMA GEMM body, k-chunk 64 (two 32-k subplanes/stage),
// 3-stage cp.async pipeline (32KB/stage). H16OUT=0: fp32 C; 1: fp16 C.
// ---------------------------------------------------------------------------
#define GEMM_SMEM 98304
template<int H16OUT>
__device__ __forceinline__ void gemm_body(
    const h16* __restrict__ A, const h16* __restrict__ B,
    float* __restrict__ C, h16* __restrict__ Ch,
    int N, int K, int lda, int ldb, int ldc, int m0, int n0, char* smem)
{
    int tid = threadIdx.x, lane = tid & 31, wid = tid >> 5;
    int mw = (wid & 1) * 64, nw = (wid >> 1) * 32;
    uint32_t s0 = smem_u32(smem);
    int nvB = min(128, N - n0);
    int nch = K >> 6;

    uint32_t rowA[4]; int sA[4];
#pragma unroll
    for (int mt = 0; mt < 4; mt++) {
        int r = mw + mt * 16 + (lane & 15);
        rowA[mt] = r * 64; sA[mt] = (r >> 1) & 3;
    }
    uint32_t rowB[2]; int sB[2];
#pragma unroll
    for (int h2 = 0; h2 < 2; h2++) {
        int r = nw + h2 * 16 + (lane & 7) + ((lane >> 4) << 3);
        rowB[h2] = r * 64; sB[h2] = (r >> 1) & 3;
    }
    int aCk = (lane >> 4) & 1, bCk = (lane >> 3) & 1;

    float acc[4][4][4];
#pragma unroll
    for (int i = 0; i < 4; i++)
#pragma unroll
        for (int j = 0; j < 4; j++)
#pragma unroll
            for (int r = 0; r < 4; r++) acc[i][j][r] = 0.f;

    // prologue: stages 0,1
#pragma unroll
    for (int pc = 0; pc < 2; pc++) {
        if (pc < nch) {
            uint32_t sb = s0 + pc * 32768;
            int k0 = pc * 64;
            load_plane(sb,         A, m0, lda, k0,      tid, 128);
            load_plane(sb + 8192,  A, m0, lda, k0 + 32, tid, 128);
            load_plane(sb + 16384, B, n0, ldb, k0,      tid, nvB);
            load_plane(sb + 24576, B, n0, ldb, k0 + 32, tid, nvB);
        }
        CP_COMMIT();
    }

    for (int c = 0; c < nch; c++) {
        CP_WAIT(1);
        __syncthreads();
        if (c + 2 < nch) {
            uint32_t sb = s0 + ((c + 2) % 3) * 32768;
            int k0 = (c + 2) * 64;
            load_plane(sb,         A, m0, lda, k0,      tid, 128);
            load_plane(sb + 8192,  A, m0, lda, k0 + 32, tid, 128);
            load_plane(sb + 16384, B, n0, ldb, k0,      tid, nvB);
            load_plane(sb + 24576, B, n0, ldb, k0 + 32, tid, nvB);
        }
        CP_COMMIT();

        uint32_t base = s0 + (c % 3) * 32768;
#pragma unroll
        for (int ks = 0; ks < 4; ks++) {
            uint32_t pA = base + (ks >> 1) * 8192;
            uint32_t pB = base + 16384 + (ks >> 1) * 8192;
            int cA = ((ks & 1) << 1) + aCk, cB = ((ks & 1) << 1) + bCk;
            uint32_t af[4][4], bf[2][4];
#pragma unroll
            for (int mt = 0; mt < 4; mt++)
                LDSM4(af[mt], pA + rowA[mt] + (uint32_t)((cA ^ sA[mt]) << 4));
#pragma unroll
            for (int h2 = 0; h2 < 2; h2++)
                LDSM4(bf[h2], pB + rowB[h2] + (uint32_t)((cB ^ sB[h2]) << 4));
#pragma unroll
            for (int mt = 0; mt < 4; mt++)
#pragma unroll
                for (int nt = 0; nt < 4; nt++)
                    MMAH(acc[mt][nt], af[mt],
                         bf[nt >> 1][(nt & 1) * 2], bf[nt >> 1][(nt & 1) * 2 + 1]);
        }
    }

#pragma unroll
    for (int mt = 0; mt < 4; mt++) {
        int r0 = m0 + mw + mt * 16 + (lane >> 2);
#pragma unroll
        for (int nt = 0; nt < 4; nt++) {
            int col = n0 + nw + nt * 8 + 2 * (lane & 3);
            if (col < N) {
                if (H16OUT == 0) {
                    float2 v0 = make_float2(acc[mt][nt][0], acc[mt][nt][1]);
                    float2 v1 = make_float2(acc[mt][nt][2], acc[mt][nt][3]);
                    *(float2*)(C + (size_t)r0 * ldc + col) = v0;
                    *(float2*)(C + (size_t)(r0 + 8) * ldc + col) = v1;
                } else {
                    *(uint32_t*)(Ch + (size_t)r0 * ldc + col) =
                        packh(acc[mt][nt][0], acc[mt][nt][1]);
                    *(uint32_t*)(Ch + (size_t)(r0 + 8) * ldc + col) =
                        packh(acc[mt][nt][2], acc[mt][nt][3]);
                }
            }
        }
    }
}

// fp32-out GEMM
__global__ void __launch_bounds__(256, 2) gemm1_k(
    const h16* __restrict__ A, const h16* __restrict__ B, float* __restrict__ C,
    int N, int K, int lda, int ldb, int ldc)
{
    extern __shared__ char smem[];
    gemm_body<0>(A, B, C, nullptr, N, K, lda, ldb, ldc,
                 blockIdx.y * 128, blockIdx.x * 128, smem);
}

// dual fp16-out GEMM (q up-proj + kv up-proj)
__global__ void __launch_bounds__(256, 2) gemm1h_dual_k(
    const h16* __restrict__ A0, const h16* __restrict__ B0, h16* __restrict__ C0,
    int N0, int K0, int lda0, int ldb0, int ldc0,
    const h16* __restrict__ A1, const h16* __restrict__ B1, h16* __restrict__ C1,
    int N1, int K1, int lda1, int ldb1, int ldc1, int nx0)
{
    extern __shared__ char smem[];
    if ((int)blockIdx.x < nx0)
        gemm_body<1>(A0, B0, nullptr, C0, N0, K0, lda0, ldb0, ldc0,
                     blockIdx.y * 128, blockIdx.x * 128, smem);
    else
        gemm_body<1>(A1, B1, nullptr, C1, N1, K1, lda1, ldb1, ldc1,
                     blockIdx.y * 128, (blockIdx.x - nx0) * 128, smem);
}

// ---------------------------------------------------------------------------
// Fused flash attention, single fp16 planes. 112KB smem -> 2 CTAs/SM.
// ---------------------------------------------------------------------------
#define FL_SMEM 114688
__global__ void __launch_bounds__(256, 2) flash_k(
    const h16* __restrict__ q_, const h16* __restrict__ kv_,
    const h16* __restrict__ kpe_,
    const float* __restrict__ mb, const int* __restrict__ pos,
    h16* __restrict__ at_)
{
    extern __shared__ char smem[];
    int bh = blockIdx.x, b = bh >> 5, h = bh & 31;
    int qi = 7 - blockIdx.y;
    int t0 = qi * 128;
    int tid = threadIdx.x, lane = tid & 31, wid = tid >> 5;
    int wrow = wid * 16;

    uint32_t S0 = smem_u32(smem);
    uint32_t Qs = S0;                  // 49152
    uint32_t Kb = S0 + 49152;          // 2 stages x 24576
    uint32_t Vb = S0 + 98304;          // 16384

    const h16* Qg = q_ + ((size_t)(b * 1024 + t0)) * 6144 + h * 192;
    const h16* KN = kv_ + (size_t)b * 1024 * 8192 + h * 256;
    const h16* KP = kpe_ + (size_t)b * 1024 * 64;
    const h16* Vg = KN + 128;
    const float* mbb = mb + b * 1024;

#pragma unroll
    for (int sp = 0; sp < 6; sp++)
        load_plane(Qs + sp * 8192, Qg, 0, 6144, sp * 32, tid, 128);
#pragma unroll
    for (int sp = 0; sp < 4; sp++)
        load_plane64(Kb + sp * 4096, KN + sp * 32, 8192, tid);
#pragma unroll
    for (int sp = 4; sp < 6; sp++)
        load_plane64(Kb + sp * 4096, KP + (sp - 4) * 32, 64, tid);
    CP_COMMIT();

    // ---- rope Q pe columns (subplanes 4,5) in smem ----
    CP_WAIT(0);
    __syncthreads();
    {
        int j = tid & 31;
        float invf = powf(10000.f, -(float)j / 32.f);
#pragma unroll
        for (int it = 0; it < 16; it++) {
            int r = (tid >> 5) + it * 8;
            uint32_t off = (uint32_t)(r * 64 +
                (((j >> 3) ^ ((r >> 1) & 3)) << 4) + (j & 7) * 2);
            h16* q4 = (h16*)(smem + 4 * 8192 + off);
            h16* q5 = (h16*)(smem + 5 * 8192 + off);
            float x1 = __half2float(*q4), x2 = __half2float(*q5);
            float p = (float)pos[b * 1024 + t0 + r];
            float sn, cs; sincosf(p * invf, &sn, &cs);
            *q4 = __float2half_rn(x1 * cs - x2 * sn);
            *q5 = __float2half_rn(x1 * sn + x2 * cs);
        }
    }

    int nst = (t0 + 128) >> 6;
    float m0 = -1e30f, m1 = -1e30f, l0 = 0.f, l1 = 0.f;
    float O[16][4];
#pragma unroll
    for (int i = 0; i < 16; i++)
#pragma unroll
        for (int j = 0; j < 4; j++) O[i][j] = 0.f;

    int rA = wrow + (lane & 15);
    int swA = (rA >> 1) & 3;
    int rB[4], swB[4];
#pragma unroll
    for (int g = 0; g < 4; g++) {
        rB[g] = g * 16 + (lane & 7) + ((lane >> 4) << 3);
        swB[g] = (rB[g] >> 1) & 3;
    }
    int aSel = (lane >> 4) & 1, bSel = (lane >> 3) & 1;
    int trow = t0 + wrow + (lane >> 2);

    for (int i = 0; i < nst; i++) {
        __syncthreads();
        load_v(Vb, Vg + (size_t)i * 64 * 8192, 8192, tid);
        CP_COMMIT();
        if (i + 1 < nst) {
            uint32_t Ks = Kb + ((i + 1) & 1) * 24576;
            size_t roff = (size_t)(i + 1) * 64;
#pragma unroll
            for (int sp = 0; sp < 4; sp++)
                load_plane64(Ks + sp * 4096, KN + roff * 8192 + sp * 32, 8192, tid);
#pragma unroll
            for (int sp = 4; sp < 6; sp++)
                load_plane64(Ks + sp * 4096, KP + roff * 64 + (sp - 4) * 32, 64, tid);
        }
        CP_COMMIT();

        CP_WAIT(2);
        __syncthreads();

        // ---- S = QK^T ----
        float S[8][4];
#pragma unroll
        for (int nt = 0; nt < 8; nt++)
#pragma unroll
            for (int j = 0; j < 4; j++) S[nt][j] = 0.f;

        uint32_t Ks = Kb + (i & 1) * 24576;
#pragma unroll
        for (int ks = 0; ks < 12; ks++) {
            int sp = ks >> 1;
            int cA = ((ks & 1) << 1) + aSel;
            int cB = ((ks & 1) << 1) + bSel;
            uint32_t ah[4], bf[4][4];
            LDSM4(ah, Qs + sp * 8192 + rA * 64 + (uint32_t)((cA ^ swA) << 4));
#pragma unroll
            for (int g = 0; g < 4; g++)
                LDSM4(bf[g], Ks + sp * 4096 + rB[g] * 64 + (uint32_t)((cB ^ swB[g]) << 4));
#pragma unroll
            for (int g = 0; g < 4; g++) {
                MMAH(S[2 * g], ah, bf[g][0], bf[g][1]);
                MMAH(S[2 * g + 1], ah, bf[g][2], bf[g][3]);
            }
        }

        // ---- online softmax ----
        int s0i = i * 64;
        float mx0 = -1e30f, mx1 = -1e30f;
#pragma unroll
        for (int nt = 0; nt < 8; nt++) {
            int sb0 = s0i + nt * 8 + ((lane & 3) << 1);
            float bias0 = mbb[sb0], bias1 = mbb[sb0 + 1];
            float v0 = S[nt][0] * SCALE_QK + bias0; if (sb0     > trow)     v0 = -1e30f;
            float v1 = S[nt][1] * SCALE_QK + bias1; if (sb0 + 1 > trow)     v1 = -1e30f;
            float v2 = S[nt][2] * SCALE_QK + bias0; if (sb0     > trow + 8) v2 = -1e30f;
            float v3 = S[nt][3] * SCALE_QK + bias1; if (sb0 + 1 > trow + 8) v3 = -1e30f;
            S[nt][0] = v0; S[nt][1] = v1; S[nt][2] = v2; S[nt][3] = v3;
            mx0 = fmaxf(mx0, fmaxf(v0, v1));
            mx1 = fmaxf(mx1, fmaxf(v2, v3));
        }
        mx0 = fmaxf(mx0, __shfl_xor_sync(0xffffffffu, mx0, 1));
        mx0 = fmaxf(mx0, __shfl_xor_sync(0xffffffffu, mx0, 2));
        mx1 = fmaxf(mx1, __shfl_xor_sync(0xffffffffu, mx1, 1));
        mx1 = fmaxf(mx1, __shfl_xor_sync(0xffffffffu, mx1, 2));
        float mn0 = fmaxf(m0, mx0), mn1 = fmaxf(m1, mx1);
        float cr0 = __expf(m0 - mn0), cr1 = __expf(m1 - mn1);
        float sum0 = 0.f, sum1 = 0.f;
#pragma unroll
        for (int nt = 0; nt < 8; nt++) {
            S[nt][0] = __expf(S[nt][0] - mn0);
            S[nt][1] = __expf(S[nt][1] - mn0);
            S[nt][2] = __expf(S[nt][2] - mn1);
            S[nt][3] = __expf(S[nt][3] - mn1);
            sum0 += S[nt][0] + S[nt][1];
            sum1 += S[nt][2] + S[nt][3];
        }
        sum0 += __shfl_xor_sync(0xffffffffu, sum0, 1);
        sum0 += __shfl_xor_sync(0xffffffffu, sum0, 2);
        sum1 += __shfl_xor_sync(0xffffffffu, sum1, 1);
        sum1 += __shfl_xor_sync(0xffffffffu, sum1, 2);
        l0 = l0 * cr0 + sum0;  l1 = l1 * cr1 + sum1;
        m0 = mn0;  m1 = mn1;
#pragma unroll
        for (int nd = 0; nd < 16; nd++) {
            O[nd][0] *= cr0; O[nd][1] *= cr0;
            O[nd][2] *= cr1; O[nd][3] *= cr1;
        }

        CP_WAIT(1);
        __syncthreads();

        // ---- O += P @ V ----
        int rV = (lane & 15);
#pragma unroll
        for (int kc = 0; kc < 4; kc++) {
            uint32_t phi[4];
#pragma unroll
            for (int j = 0; j < 2; j++) {
                int nt = 2 * kc + j;
                phi[2 * j]     = packh(S[nt][0], S[nt][1]);
                phi[2 * j + 1] = packh(S[nt][2], S[nt][3]);
            }
            int row = kc * 16 + rV;
            int sw = row & 7;
            uint32_t rbase = (uint32_t)row * 256;
            int cgrp = (lane >> 4) << 3;
#pragma unroll
            for (int g = 0; g < 8; g++) {
                int cch = (((g << 4) + cgrp) >> 3) ^ sw;
                uint32_t v4[4];
                LDSM4T(v4, Vb + rbase + (uint32_t)(cch << 4));
                MMAH_P(O[2 * g],     phi[0], phi[1], phi[2], phi[3], v4[0], v4[1]);
                MMAH_P(O[2 * g + 1], phi[0], phi[1], phi[2], phi[3], v4[2], v4[3]);
            }
        }
    }

    // ---- epilogue: O / l -> fp16 plane ----
    float inv0 = 1.f / l0, inv1 = 1.f / l1;
    size_t row0 = ((size_t)(b * 1024) + trow) * 4096 + h * 128;
    size_t row1 = row0 + (size_t)8 * 4096;
    int dcol = (lane & 3) * 2;
#pragma unroll
    for (int nd = 0; nd < 16; nd++) {
        int c = nd * 8 + dcol;
        *(uint32_t*)(at_ + row0 + c) = packh(O[nd][0] * inv0, O[nd][1] * inv0);
        *(uint32_t*)(at_ + row1 + c) = packh(O[nd][2] * inv1, O[nd][3] * inv1);
    }
}

// ------------------------- conversion / elementwise -------------------------
// Fused prologue: weight transpose+convert (5 weights) + x fp16 convert.
__global__ void prep_k(const float* __restrict__ wq_a,
                       const float* __restrict__ wkv_a,
                       const float* __restrict__ wq_b,
                       const float* __restrict__ wkv_b,
                       const float* __restrict__ wo,
                       const float* __restrict__ x,
                       h16* __restrict__ wab, h16* __restrict__ wqb,
                       h16* __restrict__ wkvb, h16* __restrict__ wot,
                       h16* __restrict__ xh)
{
    __shared__ float t[32][33];
    int bx = blockIdx.x;
    int tx = threadIdx.x, ty = threadIdx.y;
    if (bx >= 38144) {            // x convert: 32768 blocks
        long i = (long)(bx - 38144) * 256 + ty * 32 + tx;
        xh[i] = __float2half_rn(x[i]);
        return;
    }
    const float* W; h16* T; int K, N, nx, tIdx, rowOff;
    if (bx < 6144)       { W = wq_a;  T = wab;  K = 4096; N = 1536; nx = 48;  tIdx = bx;         rowOff = 0; }
    else if (bx < 8448)  { W = wkv_a; T = wab;  K = 4096; N = 576;  nx = 18;  tIdx = bx - 6144;  rowOff = 1536; }
    else if (bx < 17664) { W = wq_b;  T = wqb;  K = 1536; N = 6144; nx = 192; tIdx = bx - 8448;  rowOff = 0; }
    else if (bx < 21760) { W = wkv_b; T = wkvb; K = 512;  N = 8192; nx = 256; tIdx = bx - 17664; rowOff = 0; }
    else                 { W = wo;    T = wot;  K = 4096; N = 4096; nx = 128; tIdx = bx - 21760; rowOff = 0; }
    int n0 = (tIdx % nx) * 32, k0 = (tIdx / nx) * 32;
#pragma unroll
    for (int j = 0; j < 32; j += 8)
        t[ty + j][tx] = W[(size_t)(k0 + ty + j) * N + n0 + tx];
    __syncthreads();
#pragma unroll
    for (int j = 0; j < 32; j += 8)
        T[(size_t)(rowOff + n0 + ty + j) * K + k0 + tx] =
            __float2half_rn(t[tx][ty + j]);
}

// Fused post-down-proj: rmsnorms -> fp16, rope k_pe -> plane, mask bias.
__global__ void postdown_k(const float* __restrict__ qkv,
                           const float* __restrict__ qw,
                           const float* __restrict__ kvw,
                           const int* __restrict__ amask,
                           const int* __restrict__ pos,
                           h16* __restrict__ qlow, h16* __restrict__ kv,
                           h16* __restrict__ kpe, float* __restrict__ mb)
{
    int rb = blockIdx.x;
    int tid = threadIdx.x;
    if (rb >= 4352) {                       // mask bias: 8 blocks
        int i = (rb - 4352) * 256 + tid;
        if (i < 2048) mb[i] = amask[i] ? 0.f : -1e30f;
        return;
    }
    if (rb >= 4096) {                       // rope k_pe: 256 blocks x 8 warps
        int w = (rb - 4096) * 8 + (tid >> 5);
        int lane = tid & 31;
        const float* base = qkv + (size_t)w * 2112 + 2048;
        float p = (float)pos[w];
        float invf = powf(10000.f, -(float)lane / 32.f);
        float sn, cs; sincosf(p * invf, &sn, &cs);
        float x1 = base[lane], x2 = base[32 + lane];
        size_t ob = (size_t)w * 64;
        kpe[ob + lane]      = __float2half_rn(x1 * cs - x2 * sn);
        kpe[ob + 32 + lane] = __float2half_rn(x1 * sn + x2 * cs);
        return;
    }
    __shared__ float red[256];
    int isq = rb < 2048;
    long row = isq ? rb : rb - 2048;
    int n = isq ? 1536 : 512;
    const float* p = qkv + row * 2112 + (isq ? 0 : 1536);
    const float* w = isq ? qw : kvw;
    h16* oh = (isq ? qlow : kv) + row * n;
    float ss = 0.f;
    for (int c = tid; c < n; c += 256) { float v = p[c]; ss += v * v; }
    red[tid] = ss; __syncthreads();
    for (int s = 128; s > 0; s >>= 1) {
        if (tid < s) red[tid] += red[tid + s];
        __syncthreads();
    }
    float r = rsqrtf(red[0] / (float)n + 1e-6f);
    for (int c = tid; c < n; c += 256)
        oh[c] = __float2half_rn(p[c] * r * w[c]);
}

// ---------------------------------------------------------------------------
extern "C" void kernel_launch(void* const* d_in, const int* in_sizes, int n_in,
                              void* d_out, int out_size)
{
    const float* x        = (const float*)d_in[0];
    const float* wq_a     = (const float*)d_in[1];
    const float* q_norm_w = (const float*)d_in[2];
    const float* wq_b     = (const float*)d_in[3];
    const float* wkv_a    = (const float*)d_in[4];
    const float* kv_norm_w= (const float*)d_in[5];
    const float* wkv_b    = (const float*)d_in[6];
    const float* wo       = (const float*)d_in[7];
    const int*   amask    = (const int*)d_in[8];
    const int*   pos      = (const int*)d_in[9];
    float*       out      = (float*)d_out;

    cudaFuncSetAttribute(gemm1_k, cudaFuncAttributeMaxDynamicSharedMemorySize,
                         GEMM_SMEM);
    cudaFuncSetAttribute(gemm1h_dual_k, cudaFuncAttributeMaxDynamicSharedMemorySize,
                         GEMM_SMEM);
    cudaFuncSetAttribute(flash_k, cudaFuncAttributeMaxDynamicSharedMemorySize,
                         FL_SMEM);

    float *qkv, *mb;
    h16 *xh,*qlow,*q,*kv,*kvexp,*kpe,*at;
    h16 *wab,*wqb,*wkvb,*wot;
    cudaGetSymbolAddress((void**)&qkv,  g_qkv);
    cudaGetSymbolAddress((void**)&mb,   g_mb);
    cudaGetSymbolAddress((void**)&xh,   g_xh);
    cudaGetSymbolAddress((void**)&qlow, g_qlow);
    cudaGetSymbolAddress((void**)&q,    g_q);
    cudaGetSymbolAddress((void**)&kv,   g_kv);
    cudaGetSymbolAddress((void**)&kvexp,g_kvexp);
    cudaGetSymbolAddress((void**)&kpe,  g_kpe);
    cudaGetSymbolAddress((void**)&at,   g_at);
    cudaGetSymbolAddress((void**)&wab,  g_wab);
    cudaGetSymbolAddress((void**)&wqb,  g_wqb);
    cudaGetSymbolAddress((void**)&wkvb, g_wkvb);
    cudaGetSymbolAddress((void**)&wot,  g_wo);

    // 0. fused prologue: weight transpose+convert, x convert (single stream)
    prep_k<<<70912, dim3(32, 8)>>>(wq_a, wkv_a, wq_b, wkv_b, wo, x,
                                   wab, wqb, wkvb, wot, xh);
    // 1. merged down-proj: qkv = x @ [wq_a | wkv_a]   [2048, 2112] fp32
    gemm1_k<<<dim3(17, 16), 256, GEMM_SMEM>>>(xh, wab, qkv,
        2112, 4096, 4096, 4096, 2112);
    // 2. fused rmsnorms + rope k_pe + mask bias
    postdown_k<<<4360, 256>>>(qkv, q_norm_w, kv_norm_w, amask, pos,
                              qlow, kv, kpe, mb);
    // 3. dual up-proj -> fp16 planes
    gemm1h_dual_k<<<dim3(112, 16), 256, GEMM_SMEM>>>(
        qlow, wqb, q,      6144, 1536, 1536, 1536, 6144,
        kv,   wkvb, kvexp, 8192, 512, 512, 512, 8192, 48);
    // 4. fused attention (rope-on-load, strided K/V) -> at
    flash_k<<<dim3(64, 8), 256, FL_SMEM>>>(q, kvexp, kpe, mb, pos, at);
    // 5. out = attn @ wo
    gemm1_k<<<dim3(32, 16), 256, GEMM_SMEM>>>(at, wot, out,
        4096, 4096, 4096, 4096, 4096);
}

// round 15
// speedup vs baseline: 1.0919x; 1.0906x over previous
#include <cuda_runtime.h>
#include <cuda_fp16.h>
#include <math.h>
#include <stdint.h>

typedef __half h16;
#define TT 1024
#define SCALE_QK 0.07216878364870323f

// ------------------------- device scratch (no cudaMalloc) -------------------
__device__ float g_qkv  [2048*2112];   // qlow | kv | k_pe(fp32, pre-rope)
__device__ float g_mb   [2048];

__device__ h16 g_xh[2048*4096];
__device__ h16 g_qlow[2048*1536];
__device__ h16 g_q[2048*6144];
__device__ h16 g_kv[2048*512];
__device__ h16 g_kvexp[2048ll*8192];
__device__ h16 g_kpe[2048*64];
__device__ h16 g_at[2048*4096];
__device__ h16 g_wab[2112*4096];
__device__ h16 g_wqb[6144*1536];
__device__ h16 g_wkvb[8192*512];
__device__ h16 g_wo[4096*4096];

// ------------------------------ PTX helpers (sm_80-safe) --------------------
__device__ __forceinline__ uint32_t smem_u32(const void* p) {
    uint32_t a;
    asm("{ .reg .u64 t; cvta.to.shared.u64 t, %1; cvt.u32.u64 %0, t; }"
        : "=r"(a) : "l"(p));
    return a;
}

#define LDSM4(r, a) asm volatile( \
    "ldmatrix.sync.aligned.m8n8.x4.shared.b16 {%0,%1,%2,%3}, [%4];" \
    : "=r"((r)[0]), "=r"((r)[1]), "=r"((r)[2]), "=r"((r)[3]) : "r"(a))

#define LDSM4T(r, a) asm volatile( \
    "ldmatrix.sync.aligned.m8n8.x4.trans.shared.b16 {%0,%1,%2,%3}, [%4];" \
    : "=r"((r)[0]), "=r"((r)[1]), "=r"((r)[2]), "=r"((r)[3]) : "r"(a))

#define MMAH(d, a, b0, b1) asm volatile( \
    "mma.sync.aligned.m16n8k16.row.col.f32.f16.f16.f32 " \
    "{%0,%1,%2,%3},{%4,%5,%6,%7},{%8,%9},{%0,%1,%2,%3};" \
    : "+f"((d)[0]), "+f"((d)[1]), "+f"((d)[2]), "+f"((d)[3]) \
    : "r"((a)[0]), "r"((a)[1]), "r"((a)[2]), "r"((a)[3]), "r"(b0), "r"(b1))

#define MMAH_P(d, a0, a1, a2, a3, b0, b1) asm volatile( \
    "mma.sync.aligned.m16n8k16.row.col.f32.f16.f16.f32 " \
    "{%0,%1,%2,%3},{%4,%5,%6,%7},{%8,%9},{%0,%1,%2,%3};" \
    : "+f"((d)[0]), "+f"((d)[1]), "+f"((d)[2]), "+f"((d)[3]) \
    : "r"(a0), "r"(a1), "r"(a2), "r"(a3), "r"(b0), "r"(b1))

__device__ __forceinline__ void cpa16(uint32_t dst, const void* src, int valid) {
    int sz = valid ? 16 : 0;
    asm volatile("cp.async.cg.shared.global [%0], [%1], 16, %2;"
                 :: "r"(dst), "l"(src), "r"(sz));
}
#define CP_COMMIT() asm volatile("cp.async.commit_group;" ::: "memory")
#define CP_WAIT(n)  asm volatile("cp.async.wait_group %0;" :: "n"(n) : "memory")

__device__ __forceinline__ uint32_t packh(float a, float b) {
    __half2 t = __floats2half2_rn(a, b);
    return *reinterpret_cast<uint32_t*>(&t);
}

// Load one 128x32 h16 plane into swizzled smem (rows of 64B).
__device__ __forceinline__ void load_plane(uint32_t sb, const h16* __restrict__ G,
                                           int row0, int ld, int k0, int tid,
                                           int nvalid) {
#pragma unroll
    for (int i = 0; i < 2; i++) {
        int idx = tid * 2 + i;
        int r = idx >> 2, c = idx & 3;
        uint32_t dst = sb + r * 64 + ((c ^ ((r >> 1) & 3)) << 4);
        int ok = r < nvalid;
        const h16* src = G + (size_t)(row0 + (ok ? r : 0)) * ld + k0 + c * 8;
        cpa16(dst, src, ok);
    }
}

// Load one 64x32 h16 subplane (256 threads -> 1 line each). G pre-offset.
__device__ __forceinline__ void load_plane64(uint32_t sb, const h16* __restrict__ G,
                                             int ld, int tid) {
    int r = tid >> 2, c = tid & 3;
    uint32_t dst = sb + r * 64 + ((c ^ ((r >> 1) & 3)) << 4);
    cpa16(dst, G + (size_t)r * ld + c * 8, 1);
}

// Load one 64x128 h16 V plane (rows of 256B) with row-xor swizzle; row stride ld.
__device__ __forceinline__ void load_v(uint32_t sb, const h16* __restrict__ G,
                                       int ld, int tid) {
#pragma unroll
    for (int i = 0; i < 4; i++) {
        int idx = i * 256 + tid;
        int r = idx >> 4, c = idx & 15;
        uint32_t dst = sb + r * 256 + ((c ^ (r & 7)) << 4);
        cpa16(dst, G + (size_t)r * ld + c * 8, 1);
    }
}

// ---------------------------------------------------------------------------
// Single-pass fp16 HMMA GEMM body, k-chunk 32, 4-stage cp.async pipeline
// (16KB/stage). H16OUT=0: fp32 C; H16OUT=1: fp16 C.   [R12 configuration]
// ---------------------------------------------------------------------------
#define GEMM_SMEM 65536
template<int H16OUT>
__device__ __forceinline__ void gemm_body(
    const h16* __restrict__ A, const h16* __restrict__ B,
    float* __restrict__ C, h16* __restrict__ Ch,
    int N, int K, int lda, int ldb, int ldc, int m0, int n0, char* smem)
{
    int tid = threadIdx.x, lane = tid & 31, wid = tid >> 5;
    int mw = (wid & 1) * 64, nw = (wid >> 1) * 32;
    uint32_t s0 = smem_u32(smem);
    int nvB = min(128, N - n0);
    int nch = K >> 5;

    uint32_t rowA[4]; int sA[4];
#pragma unroll
    for (int mt = 0; mt < 4; mt++) {
        int r = mw + mt * 16 + (lane & 15);
        rowA[mt] = r * 64; sA[mt] = (r >> 1) & 3;
    }
    uint32_t rowB[2]; int sB[2];
#pragma unroll
    for (int h2 = 0; h2 < 2; h2++) {
        int r = nw + h2 * 16 + (lane & 7) + ((lane >> 4) << 3);
        rowB[h2] = r * 64; sB[h2] = (r >> 1) & 3;
    }
    int aCk = (lane >> 4) & 1, bCk = (lane >> 3) & 1;

    float acc[4][4][4];
#pragma unroll
    for (int i = 0; i < 4; i++)
#pragma unroll
        for (int j = 0; j < 4; j++)
#pragma unroll
            for (int r = 0; r < 4; r++) acc[i][j][r] = 0.f;

    // prologue: stages 0..2
#pragma unroll
    for (int pc = 0; pc < 3; pc++) {
        if (pc < nch) {
            uint32_t sb = s0 + pc * 16384;
            load_plane(sb,        A, m0, lda, pc * 32, tid, 128);
            load_plane(sb + 8192, B, n0, ldb, pc * 32, tid, nvB);
        }
        CP_COMMIT();
    }

    for (int c = 0; c < nch; c++) {
        CP_WAIT(2);
        __syncthreads();
        if (c + 3 < nch) {
            uint32_t sb = s0 + ((c + 3) & 3) * 16384;
            int k0 = (c + 3) * 32;
            load_plane(sb,        A, m0, lda, k0, tid, 128);
            load_plane(sb + 8192, B, n0, ldb, k0, tid, nvB);
        }
        CP_COMMIT();

        uint32_t base = s0 + (c & 3) * 16384;
        uint32_t pA = base, pB = base + 8192;
#pragma unroll
        for (int ks = 0; ks < 2; ks++) {
            uint32_t af[4][4], bf[2][4];
            int cA = ks * 2 + aCk, cB = ks * 2 + bCk;
#pragma unroll
            for (int mt = 0; mt < 4; mt++)
                LDSM4(af[mt], pA + rowA[mt] + (uint32_t)((cA ^ sA[mt]) << 4));
#pragma unroll
            for (int h2 = 0; h2 < 2; h2++)
                LDSM4(bf[h2], pB + rowB[h2] + (uint32_t)((cB ^ sB[h2]) << 4));
#pragma unroll
            for (int mt = 0; mt < 4; mt++)
#pragma unroll
                for (int nt = 0; nt < 4; nt++)
                    MMAH(acc[mt][nt], af[mt],
                         bf[nt >> 1][(nt & 1) * 2], bf[nt >> 1][(nt & 1) * 2 + 1]);
        }
    }

#pragma unroll
    for (int mt = 0; mt < 4; mt++) {
        int r0 = m0 + mw + mt * 16 + (lane >> 2);
#pragma unroll
        for (int nt = 0; nt < 4; nt++) {
            int col = n0 + nw + nt * 8 + 2 * (lane & 3);
            if (col < N) {
                if (H16OUT == 0) {
                    float2 v0 = make_float2(acc[mt][nt][0], acc[mt][nt][1]);
                    float2 v1 = make_float2(acc[mt][nt][2], acc[mt][nt][3]);
                    *(float2*)(C + (size_t)r0 * ldc + col) = v0;
                    *(float2*)(C + (size_t)(r0 + 8) * ldc + col) = v1;
                } else {
                    *(uint32_t*)(Ch + (size_t)r0 * ldc + col) =
                        packh(acc[mt][nt][0], acc[mt][nt][1]);
                    *(uint32_t*)(Ch + (size_t)(r0 + 8) * ldc + col) =
                        packh(acc[mt][nt][2], acc[mt][nt][3]);
                }
            }
        }
    }
}

// fp32-out GEMM
__global__ void __launch_bounds__(256, 2) gemm1_k(
    const h16* __restrict__ A, const h16* __restrict__ B, float* __restrict__ C,
    int N, int K, int lda, int ldb, int ldc)
{
    extern __shared__ char smem[];
    gemm_body<0>(A, B, C, nullptr, N, K, lda, ldb, ldc,
                 blockIdx.y * 128, blockIdx.x * 128, smem);
}

// dual fp16-out GEMM (q up-proj + kv up-proj)
__global__ void __launch_bounds__(256, 2) gemm1h_dual_k(
    const h16* __restrict__ A0, const h16* __restrict__ B0, h16* __restrict__ C0,
    int N0, int K0, int lda0, int ldb0, int ldc0,
    const h16* __restrict__ A1, const h16* __restrict__ B1, h16* __restrict__ C1,
    int N1, int K1, int lda1, int ldb1, int ldc1, int nx0)
{
    extern __shared__ char smem[];
    if ((int)blockIdx.x < nx0)
        gemm_body<1>(A0, B0, nullptr, C0, N0, K0, lda0, ldb0, ldc0,
                     blockIdx.y * 128, blockIdx.x * 128, smem);
    else
        gemm_body<1>(A1, B1, nullptr, C1, N1, K1, lda1, ldb1, ldc1,
                     blockIdx.y * 128, (blockIdx.x - nx0) * 128, smem);
}

// ---------------------------------------------------------------------------
// Fused flash attention, single fp16 planes. 112KB smem -> 2 CTAs/SM.
// ---------------------------------------------------------------------------
#define FL_SMEM 114688
__global__ void __launch_bounds__(256, 2) flash_k(
    const h16* __restrict__ q_, const h16* __restrict__ kv_,
    const h16* __restrict__ kpe_,
    const float* __restrict__ mb, const int* __restrict__ pos,
    h16* __restrict__ at_)
{
    extern __shared__ char smem[];
    int bh = blockIdx.x, b = bh >> 5, h = bh & 31;
    int qi = 7 - blockIdx.y;
    int t0 = qi * 128;
    int tid = threadIdx.x, lane = tid & 31, wid = tid >> 5;
    int wrow = wid * 16;

    uint32_t S0 = smem_u32(smem);
    uint32_t Qs = S0;                  // 49152
    uint32_t Kb = S0 + 49152;          // 2 stages x 24576
    uint32_t Vb = S0 + 98304;          // 16384

    const h16* Qg = q_ + ((size_t)(b * 1024 + t0)) * 6144 + h * 192;
    const h16* KN = kv_ + (size_t)b * 1024 * 8192 + h * 256;
    const h16* KP = kpe_ + (size_t)b * 1024 * 64;
    const h16* Vg = KN + 128;
    const float* mbb = mb + b * 1024;

#pragma unroll
    for (int sp = 0; sp < 6; sp++)
        load_plane(Qs + sp * 8192, Qg, 0, 6144, sp * 32, tid, 128);
#pragma unroll
    for (int sp = 0; sp < 4; sp++)
        load_plane64(Kb + sp * 4096, KN + sp * 32, 8192, tid);
#pragma unroll
    for (int sp = 4; sp < 6; sp++)
        load_plane64(Kb + sp * 4096, KP + (sp - 4) * 32, 64, tid);
    CP_COMMIT();

    // ---- rope Q pe columns (subplanes 4,5) in smem ----
    CP_WAIT(0);
    __syncthreads();
    {
        int j = tid & 31;
        float invf = powf(10000.f, -(float)j / 32.f);
#pragma unroll
        for (int it = 0; it < 16; it++) {
            int r = (tid >> 5) + it * 8;
            uint32_t off = (uint32_t)(r * 64 +
                (((j >> 3) ^ ((r >> 1) & 3)) << 4) + (j & 7) * 2);
            h16* q4 = (h16*)(smem + 4 * 8192 + off);
            h16* q5 = (h16*)(smem + 5 * 8192 + off);
            float x1 = __half2float(*q4), x2 = __half2float(*q5);
            float p = (float)pos[b * 1024 + t0 + r];
            float sn, cs; sincosf(p * invf, &sn, &cs);
            *q4 = __float2half_rn(x1 * cs - x2 * sn);
            *q5 = __float2half_rn(x1 * sn + x2 * cs);
        }
    }

    int nst = (t0 + 128) >> 6;
    float m0 = -1e30f, m1 = -1e30f, l0 = 0.f, l1 = 0.f;
    float O[16][4];
#pragma unroll
    for (int i = 0; i < 16; i++)
#pragma unroll
        for (int j = 0; j < 4; j++) O[i][j] = 0.f;

    int rA = wrow + (lane & 15);
    int swA = (rA >> 1) & 3;
    int rB[4], swB[4];
#pragma unroll
    for (int g = 0; g < 4; g++) {
        rB[g] = g * 16 + (lane & 7) + ((lane >> 4) << 3);
        swB[g] = (rB[g] >> 1) & 3;
    }
    int aSel = (lane >> 4) & 1, bSel = (lane >> 3) & 1;
    int trow = t0 + wrow + (lane >> 2);

    for (int i = 0; i < nst; i++) {
        __syncthreads();
        load_v(Vb, Vg + (size_t)i * 64 * 8192, 8192, tid);
        CP_COMMIT();
        if (i + 1 < nst) {
            uint32_t Ks = Kb + ((i + 1) & 1) * 24576;
            size_t roff = (size_t)(i + 1) * 64;
#pragma unroll
            for (int sp = 0; sp < 4; sp++)
                load_plane64(Ks + sp * 4096, KN + roff * 8192 + sp * 32, 8192, tid);
#pragma unroll
            for (int sp = 4; sp < 6; sp++)
                load_plane64(Ks + sp * 4096, KP + roff * 64 + (sp - 4) * 32, 64, tid);
        }
        CP_COMMIT();

        CP_WAIT(2);
        __syncthreads();

        // ---- S = QK^T ----
        float S[8][4];
#pragma unroll
        for (int nt = 0; nt < 8; nt++)
#pragma unroll
            for (int j = 0; j < 4; j++) S[nt][j] = 0.f;

        uint32_t Ks = Kb + (i & 1) * 24576;
#pragma unroll
        for (int ks = 0; ks < 12; ks++) {
            int sp = ks >> 1;
            int cA = ((ks & 1) << 1) + aSel;
            int cB = ((ks & 1) << 1) + bSel;
            uint32_t ah[4], bf[4][4];
            LDSM4(ah, Qs + sp * 8192 + rA * 64 + (uint32_t)((cA ^ swA) << 4));
#pragma unroll
            for (int g = 0; g < 4; g++)
                LDSM4(bf[g], Ks + sp * 4096 + rB[g] * 64 + (uint32_t)((cB ^ swB[g]) << 4));
#pragma unroll
            for (int g = 0; g < 4; g++) {
                MMAH(S[2 * g], ah, bf[g][0], bf[g][1]);
                MMAH(S[2 * g + 1], ah, bf[g][2], bf[g][3]);
            }
        }

        // ---- online softmax ----
        int s0i = i * 64;
        float mx0 = -1e30f, mx1 = -1e30f;
#pragma unroll
        for (int nt = 0; nt < 8; nt++) {
            int sb0 = s0i + nt * 8 + ((lane & 3) << 1);
            float bias0 = mbb[sb0], bias1 = mbb[sb0 + 1];
            float v0 = S[nt][0] * SCALE_QK + bias0; if (sb0     > trow)     v0 = -1e30f;
            float v1 = S[nt][1] * SCALE_QK + bias1; if (sb0 + 1 > trow)     v1 = -1e30f;
            float v2 = S[nt][2] * SCALE_QK + bias0; if (sb0     > trow + 8) v2 = -1e30f;
            float v3 = S[nt][3] * SCALE_QK + bias1; if (sb0 + 1 > trow + 8) v3 = -1e30f;
            S[nt][0] = v0; S[nt][1] = v1; S[nt][2] = v2; S[nt][3] = v3;
            mx0 = fmaxf(mx0, fmaxf(v0, v1));
            mx1 = fmaxf(mx1, fmaxf(v2, v3));
        }
        mx0 = fmaxf(mx0, __shfl_xor_sync(0xffffffffu, mx0, 1));
        mx0 = fmaxf(mx0, __shfl_xor_sync(0xffffffffu, mx0, 2));
        mx1 = fmaxf(mx1, __shfl_xor_sync(0xffffffffu, mx1, 1));
        mx1 = fmaxf(mx1, __shfl_xor_sync(0xffffffffu, mx1, 2));
        float mn0 = fmaxf(m0, mx0), mn1 = fmaxf(m1, mx1);
        float cr0 = __expf(m0 - mn0), cr1 = __expf(m1 - mn1);
        float sum0 = 0.f, sum1 = 0.f;
#pragma unroll
        for (int nt = 0; nt < 8; nt++) {
            S[nt][0] = __expf(S[nt][0] - mn0);
            S[nt][1] = __expf(S[nt][1] - mn0);
            S[nt][2] = __expf(S[nt][2] - mn1);
            S[nt][3] = __expf(S[nt][3] - mn1);
            sum0 += S[nt][0] + S[nt][1];
            sum1 += S[nt][2] + S[nt][3];
        }
        sum0 += __shfl_xor_sync(0xffffffffu, sum0, 1);
        sum0 += __shfl_xor_sync(0xffffffffu, sum0, 2);
        sum1 += __shfl_xor_sync(0xffffffffu, sum1, 1);
        sum1 += __shfl_xor_sync(0xffffffffu, sum1, 2);
        l0 = l0 * cr0 + sum0;  l1 = l1 * cr1 + sum1;
        m0 = mn0;  m1 = mn1;
#pragma unroll
        for (int nd = 0; nd < 16; nd++) {
            O[nd][0] *= cr0; O[nd][1] *= cr0;
            O[nd][2] *= cr1; O[nd][3] *= cr1;
        }

        CP_WAIT(1);
        __syncthreads();

        // ---- O += P @ V ----
        int rV = (lane & 15);
#pragma unroll
        for (int kc = 0; kc < 4; kc++) {
            uint32_t phi[4];
#pragma unroll
            for (int j = 0; j < 2; j++) {
                int nt = 2 * kc + j;
                phi[2 * j]     = packh(S[nt][0], S[nt][1]);
                phi[2 * j + 1] = packh(S[nt][2], S[nt][3]);
            }
            int row = kc * 16 + rV;
            int sw = row & 7;
            uint32_t rbase = (uint32_t)row * 256;
            int cgrp = (lane >> 4) << 3;
#pragma unroll
            for (int g = 0; g < 8; g++) {
                int cch = (((g << 4) + cgrp) >> 3) ^ sw;
                uint32_t v4[4];
                LDSM4T(v4, Vb + rbase + (uint32_t)(cch << 4));
                MMAH_P(O[2 * g],     phi[0], phi[1], phi[2], phi[3], v4[0], v4[1]);
                MMAH_P(O[2 * g + 1], phi[0], phi[1], phi[2], phi[3], v4[2], v4[3]);
            }
        }
    }

    // ---- epilogue: O / l -> fp16 plane ----
    float inv0 = 1.f / l0, inv1 = 1.f / l1;
    size_t row0 = ((size_t)(b * 1024) + trow) * 4096 + h * 128;
    size_t row1 = row0 + (size_t)8 * 4096;
    int dcol = (lane & 3) * 2;
#pragma unroll
    for (int nd = 0; nd < 16; nd++) {
        int c = nd * 8 + dcol;
        *(uint32_t*)(at_ + row0 + c) = packh(O[nd][0] * inv0, O[nd][1] * inv0);
        *(uint32_t*)(at_ + row1 + c) = packh(O[nd][2] * inv1, O[nd][3] * inv1);
    }
}

// ------------------------- conversion / elementwise -------------------------
// Fused prologue: weight transpose+convert (5 weights) + vectorized x convert.
__global__ void prep_k(const float* __restrict__ wq_a,
                       const float* __restrict__ wkv_a,
                       const float* __restrict__ wq_b,
                       const float* __restrict__ wkv_b,
                       const float* __restrict__ wo,
                       const float* __restrict__ x,
                       h16* __restrict__ wab, h16* __restrict__ wqb,
                       h16* __restrict__ wkvb, h16* __restrict__ wot,
                       h16* __restrict__ xh)
{
    __shared__ float t[32][33];
    int bx = blockIdx.x;
    int tx = threadIdx.x, ty = threadIdx.y;
    if (bx >= 38144) {            // x convert, 4 elems/thread: 8192 blocks
        long i = ((long)(bx - 38144) * 256 + ty * 32 + tx) * 4;
        float4 v = *(const float4*)(x + i);
        uint2 o = make_uint2(packh(v.x, v.y), packh(v.z, v.w));
        *(uint2*)(xh + i) = o;
        return;
    }
    const float* W; h16* T; int K, N, nx, tIdx, rowOff;
    if (bx < 6144)       { W = wq_a;  T = wab;  K = 4096; N = 1536; nx = 48;  tIdx = bx;         rowOff = 0; }
    else if (bx < 8448)  { W = wkv_a; T = wab;  K = 4096; N = 576;  nx = 18;  tIdx = bx - 6144;  rowOff = 1536; }
    else if (bx < 17664) { W = wq_b;  T = wqb;  K = 1536; N = 6144; nx = 192; tIdx = bx - 8448;  rowOff = 0; }
    else if (bx < 21760) { W = wkv_b; T = wkvb; K = 512;  N = 8192; nx = 256; tIdx = bx - 17664; rowOff = 0; }
    else                 { W = wo;    T = wot;  K = 4096; N = 4096; nx = 128; tIdx = bx - 21760; rowOff = 0; }
    int n0 = (tIdx % nx) * 32, k0 = (tIdx / nx) * 32;
#pragma unroll
    for (int j = 0; j < 32; j += 8)
        t[ty + j][tx] = W[(size_t)(k0 + ty + j) * N + n0 + tx];
    __syncthreads();
#pragma unroll
    for (int j = 0; j < 32; j += 8)
        T[(size_t)(rowOff + n0 + ty + j) * K + k0 + tx] =
            __float2half_rn(t[tx][ty + j]);
}

// Fused post-down-proj: rmsnorms -> fp16, rope k_pe -> plane, mask bias.
__global__ void postdown_k(const float* __restrict__ qkv,
                           const float* __restrict__ qw,
                           const float* __restrict__ kvw,
                           const int* __restrict__ amask,
                           const int* __restrict__ pos,
                           h16* __restrict__ qlow, h16* __restrict__ kv,
                           h16* __restrict__ kpe, float* __restrict__ mb)
{
    int rb = blockIdx.x;
    int tid = threadIdx.x;
    if (rb >= 4352) {                       // mask bias: 8 blocks
        int i = (rb - 4352) * 256 + tid;
        if (i < 2048) mb[i] = amask[i] ? 0.f : -1e30f;
        return;
    }
    if (rb >= 4096) {                       // rope k_pe: 256 blocks x 8 warps
        int w = (rb - 4096) * 8 + (tid >> 5);
        int lane = tid & 31;
        const float* base = qkv + (size_t)w * 2112 + 2048;
        float p = (float)pos[w];
        float invf = powf(10000.f, -(float)lane / 32.f);
        float sn, cs; sincosf(p * invf, &sn, &cs);
        float x1 = base[lane], x2 = base[32 + lane];
        size_t ob = (size_t)w * 64;
        kpe[ob + lane]      = __float2half_rn(x1 * cs - x2 * sn);
        kpe[ob + 32 + lane] = __float2half_rn(x1 * sn + x2 * cs);
        return;
    }
    __shared__ float red[256];
    int isq = rb < 2048;
    long row = isq ? rb : rb - 2048;
    int n = isq ? 1536 : 512;
    const float* p = qkv + row * 2112 + (isq ? 0 : 1536);
    const float* w = isq ? qw : kvw;
    h16* oh = (isq ? qlow : kv) + row * n;
    float ss = 0.f;
    for (int c = tid; c < n; c += 256) { float v = p[c]; ss += v * v; }
    red[tid] = ss; __syncthreads();
    for (int s = 128; s > 0; s >>= 1) {
        if (tid < s) red[tid] += red[tid + s];
        __syncthreads();
    }
    float r = rsqrtf(red[0] / (float)n + 1e-6f);
    for (int c = tid; c < n; c += 256)
        oh[c] = __float2half_rn(p[c] * r * w[c]);
}

// ---------------------------------------------------------------------------
extern "C" void kernel_launch(void* const* d_in, const int* in_sizes, int n_in,
                              void* d_out, int out_size)
{
    const float* x        = (const float*)d_in[0];
    const float* wq_a     = (const float*)d_in[1];
    const float* q_norm_w = (const float*)d_in[2];
    const float* wq_b     = (const float*)d_in[3];
    const float* wkv_a    = (const float*)d_in[4];
    const float* kv_norm_w= (const float*)d_in[5];
    const float* wkv_b    = (const float*)d_in[6];
    const float* wo       = (const float*)d_in[7];
    const int*   amask    = (const int*)d_in[8];
    const int*   pos      = (const int*)d_in[9];
    float*       out      = (float*)d_out;

    cudaFuncSetAttribute(gemm1_k, cudaFuncAttributeMaxDynamicSharedMemorySize,
                         GEMM_SMEM);
    cudaFuncSetAttribute(gemm1h_dual_k, cudaFuncAttributeMaxDynamicSharedMemorySize,
                         GEMM_SMEM);
    cudaFuncSetAttribute(flash_k, cudaFuncAttributeMaxDynamicSharedMemorySize,
                         FL_SMEM);

    float *qkv, *mb;
    h16 *xh,*qlow,*q,*kv,*kvexp,*kpe,*at;
    h16 *wab,*wqb,*wkvb,*wot;
    cudaGetSymbolAddress((void**)&qkv,  g_qkv);
    cudaGetSymbolAddress((void**)&mb,   g_mb);
    cudaGetSymbolAddress((void**)&xh,   g_xh);
    cudaGetSymbolAddress((void**)&qlow, g_qlow);
    cudaGetSymbolAddress((void**)&q,    g_q);
    cudaGetSymbolAddress((void**)&kv,   g_kv);
    cudaGetSymbolAddress((void**)&kvexp,g_kvexp);
    cudaGetSymbolAddress((void**)&kpe,  g_kpe);
    cudaGetSymbolAddress((void**)&at,   g_at);
    cudaGetSymbolAddress((void**)&wab,  g_wab);
    cudaGetSymbolAddress((void**)&wqb,  g_wqb);
    cudaGetSymbolAddress((void**)&wkvb, g_wkvb);
    cudaGetSymbolAddress((void**)&wot,  g_wo);

    // 0. fused prologue: weight transpose+convert, x convert (single stream)
    prep_k<<<46336, dim3(32, 8)>>>(wq_a, wkv_a, wq_b, wkv_b, wo, x,
                                   wab, wqb, wkvb, wot, xh);
    // 1. merged down-proj: qkv = x @ [wq_a | wkv_a]   [2048, 2112] fp32
    gemm1_k<<<dim3(17, 16), 256, GEMM_SMEM>>>(xh, wab, qkv,
        2112, 4096, 4096, 4096, 2112);
    // 2. fused rmsnorms + rope k_pe + mask bias
    postdown_k<<<4360, 256>>>(qkv, q_norm_w, kv_norm_w, amask, pos,
                              qlow, kv, kpe, mb);
    // 3. dual up-proj -> fp16 planes
    gemm1h_dual_k<<<dim3(112, 16), 256, GEMM_SMEM>>>(
        qlow, wqb, q,      6144, 1536, 1536, 1536, 6144,
        kv,   wkvb, kvexp, 8192, 512, 512, 512, 8192, 48);
    // 4. fused attention (rope-on-load, strided K/V) -> at
    flash_k<<<dim3(64, 8), 256, FL_SMEM>>>(q, kvexp, kpe, mb, pos, at);
    // 5. out = attn @ wo
    gemm1_k<<<dim3(32, 16), 256, GEMM_SMEM>>>(at, wot, out,
        4096, 4096, 4096, 4096, 4096);
}

// round 16
// speedup vs baseline: 1.1906x; 1.0904x over previous
#include <cuda_runtime.h>
#include <cuda_fp16.h>
#include <math.h>
#include <stdint.h>

typedef __half h16;
#define TT 1024
#define SCALE_QK 0.07216878364870323f

// ------------------------- device scratch (no cudaMalloc) -------------------
__device__ float g_qkv  [2048*2112];   // qlow | kv | k_pe(fp32, pre-rope)
__device__ float g_mb   [2048];

__device__ h16 g_xh[2048*4096];
__device__ h16 g_qlow[2048*1536];
__device__ h16 g_q[2048*6144];
__device__ h16 g_kv[2048*512];
__device__ h16 g_kvexp[2048ll*8192];
__device__ h16 g_kpe[2048*64];
__device__ h16 g_at[2048*4096];
__device__ h16 g_wqa[4096*1536];       // K-row-major (natural layout)
__device__ h16 g_wkva[4096*576];
__device__ h16 g_wqb[1536*6144];
__device__ h16 g_wkvb[512*8192];
__device__ h16 g_wo[4096*4096];

// ------------------------------ PTX helpers (sm_80-safe) --------------------
__device__ __forceinline__ uint32_t smem_u32(const void* p) {
    uint32_t a;
    asm("{ .reg .u64 t; cvta.to.shared.u64 t, %1; cvt.u32.u64 %0, t; }"
        : "=r"(a) : "l"(p));
    return a;
}

#define LDSM4(r, a) asm volatile( \
    "ldmatrix.sync.aligned.m8n8.x4.shared.b16 {%0,%1,%2,%3}, [%4];" \
    : "=r"((r)[0]), "=r"((r)[1]), "=r"((r)[2]), "=r"((r)[3]) : "r"(a))

#define LDSM4T(r, a) asm volatile( \
    "ldmatrix.sync.aligned.m8n8.x4.trans.shared.b16 {%0,%1,%2,%3}, [%4];" \
    : "=r"((r)[0]), "=r"((r)[1]), "=r"((r)[2]), "=r"((r)[3]) : "r"(a))

#define MMAH(d, a, b0, b1) asm volatile( \
    "mma.sync.aligned.m16n8k16.row.col.f32.f16.f16.f32 " \
    "{%0,%1,%2,%3},{%4,%5,%6,%7},{%8,%9},{%0,%1,%2,%3};" \
    : "+f"((d)[0]), "+f"((d)[1]), "+f"((d)[2]), "+f"((d)[3]) \
    : "r"((a)[0]), "r"((a)[1]), "r"((a)[2]), "r"((a)[3]), "r"(b0), "r"(b1))

#define MMAH_P(d, a0, a1, a2, a3, b0, b1) asm volatile( \
    "mma.sync.aligned.m16n8k16.row.col.f32.f16.f16.f32 " \
    "{%0,%1,%2,%3},{%4,%5,%6,%7},{%8,%9},{%0,%1,%2,%3};" \
    : "+f"((d)[0]), "+f"((d)[1]), "+f"((d)[2]), "+f"((d)[3]) \
    : "r"(a0), "r"(a1), "r"(a2), "r"(a3), "r"(b0), "r"(b1))

__device__ __forceinline__ void cpa16(uint32_t dst, const void* src, int valid) {
    int sz = valid ? 16 : 0;
    asm volatile("cp.async.cg.shared.global [%0], [%1], 16, %2;"
                 :: "r"(dst), "l"(src), "r"(sz));
}
#define CP_COMMIT() asm volatile("cp.async.commit_group;" ::: "memory")
#define CP_WAIT(n)  asm volatile("cp.async.wait_group %0;" :: "n"(n) : "memory")

__device__ __forceinline__ uint32_t packh(float a, float b) {
    __half2 t = __floats2half2_rn(a, b);
    return *reinterpret_cast<uint32_t*>(&t);
}

// Load one 128x32 h16 A plane into swizzled smem (rows of 64B).
__device__ __forceinline__ void load_plane(uint32_t sb, const h16* __restrict__ G,
                                           int row0, int ld, int k0, int tid,
                                           int nvalid) {
#pragma unroll
    for (int i = 0; i < 2; i++) {
        int idx = tid * 2 + i;
        int r = idx >> 2, c = idx & 3;
        uint32_t dst = sb + r * 64 + ((c ^ ((r >> 1) & 3)) << 4);
        int ok = r < nvalid;
        const h16* src = G + (size_t)(row0 + (ok ? r : 0)) * ld + k0 + c * 8;
        cpa16(dst, src, ok);
    }
}

// Load one 32(k-rows) x 128(n-cols) B tile from W[K][N] (row stride ldb)
// into smem rows of 256B with row-xor swizzle; zero-fill n-cols >= nrem.
__device__ __forceinline__ void load_planeB(uint32_t sb, const h16* __restrict__ G,
                                            int n0, int ldb, int k0, int tid,
                                            int nrem) {
#pragma unroll
    for (int i = 0; i < 2; i++) {
        int idx = i * 256 + tid;
        int r = idx >> 4, c = idx & 15;
        uint32_t dst = sb + r * 256 + ((c ^ (r & 7)) << 4);
        int ok = c * 8 < nrem;
        const h16* src = G + (size_t)(k0 + r) * ldb + n0 + (ok ? c * 8 : 0);
        cpa16(dst, src, ok);
    }
}

// Load one 64x32 h16 subplane (256 threads -> 1 line each). G pre-offset.
__device__ __forceinline__ void load_plane64(uint32_t sb, const h16* __restrict__ G,
                                             int ld, int tid) {
    int r = tid >> 2, c = tid & 3;
    uint32_t dst = sb + r * 64 + ((c ^ ((r >> 1) & 3)) << 4);
    cpa16(dst, G + (size_t)r * ld + c * 8, 1);
}

// Load one 64x128 h16 V plane (rows of 256B) with row-xor swizzle; row stride ld.
__device__ __forceinline__ void load_v(uint32_t sb, const h16* __restrict__ G,
                                       int ld, int tid) {
#pragma unroll
    for (int i = 0; i < 4; i++) {
        int idx = i * 256 + tid;
        int r = idx >> 4, c = idx & 15;
        uint32_t dst = sb + r * 256 + ((c ^ (r & 7)) << 4);
        cpa16(dst, G + (size_t)r * ld + c * 8, 1);
    }
}

// ---------------------------------------------------------------------------
// Single-pass fp16 HMMA GEMM, B in natural [K][N] layout via ldmatrix.trans.
// k-chunk 32, 4-stage cp.async (16KB/stage). H16OUT=0: fp32 C; 1: fp16 C.
// ---------------------------------------------------------------------------
#define GEMM_SMEM 65536
template<int H16OUT>
__device__ __forceinline__ void gemm_body(
    const h16* __restrict__ A, const h16* __restrict__ B,
    float* __restrict__ C, h16* __restrict__ Ch,
    int N, int K, int lda, int ldb, int ldc, int m0, int n0, char* smem)
{
    int tid = threadIdx.x, lane = tid & 31, wid = tid >> 5;
    int mw = (wid & 1) * 64, nw = (wid >> 1) * 32;
    uint32_t s0 = smem_u32(smem);
    int nvB = min(128, N - n0);
    int nch = K >> 5;

    uint32_t rowA[4]; int sA[4];
#pragma unroll
    for (int mt = 0; mt < 4; mt++) {
        int r = mw + mt * 16 + (lane & 15);
        rowA[mt] = r * 64; sA[mt] = (r >> 1) & 3;
    }
    int aCk = (lane >> 4) & 1;

    // B fragment addressing (cloned from flash PV ldmatrix.trans path)
    int rVb = lane & 15, cgrpb = (lane >> 4) << 3;
    int swb = rVb & 7;
    uint32_t rowBb = (uint32_t)rVb * 256;
    uint32_t cchB[2];
#pragma unroll
    for (int g = 0; g < 2; g++)
        cchB[g] = (uint32_t)(((((nw + (g << 4) + cgrpb) >> 3) ^ swb) << 4));

    float acc[4][4][4];
#pragma unroll
    for (int i = 0; i < 4; i++)
#pragma unroll
        for (int j = 0; j < 4; j++)
#pragma unroll
            for (int r = 0; r < 4; r++) acc[i][j][r] = 0.f;

    // prologue: stages 0..2
#pragma unroll
    for (int pc = 0; pc < 3; pc++) {
        if (pc < nch) {
            uint32_t sb = s0 + pc * 16384;
            load_plane (sb,        A, m0, lda, pc * 32, tid, 128);
            load_planeB(sb + 8192, B, n0, ldb, pc * 32, tid, nvB);
        }
        CP_COMMIT();
    }

    for (int c = 0; c < nch; c++) {
        CP_WAIT(2);
        __syncthreads();
        if (c + 3 < nch) {
            uint32_t sb = s0 + ((c + 3) & 3) * 16384;
            int k0 = (c + 3) * 32;
            load_plane (sb,        A, m0, lda, k0, tid, 128);
            load_planeB(sb + 8192, B, n0, ldb, k0, tid, nvB);
        }
        CP_COMMIT();

        uint32_t base = s0 + (c & 3) * 16384;
        uint32_t pA = base, pB = base + 8192;
#pragma unroll
        for (int ks = 0; ks < 2; ks++) {
            uint32_t af[4][4], bf[2][4];
            int cA = ks * 2 + aCk;
#pragma unroll
            for (int mt = 0; mt < 4; mt++)
                LDSM4(af[mt], pA + rowA[mt] + (uint32_t)((cA ^ sA[mt]) << 4));
#pragma unroll
            for (int g = 0; g < 2; g++)
                LDSM4T(bf[g], pB + (uint32_t)(ks * 4096) + rowBb + cchB[g]);
#pragma unroll
            for (int mt = 0; mt < 4; mt++)
#pragma unroll
                for (int nt = 0; nt < 4; nt++)
                    MMAH(acc[mt][nt], af[mt],
                         bf[nt >> 1][(nt & 1) * 2], bf[nt >> 1][(nt & 1) * 2 + 1]);
        }
    }

#pragma unroll
    for (int mt = 0; mt < 4; mt++) {
        int r0 = m0 + mw + mt * 16 + (lane >> 2);
#pragma unroll
        for (int nt = 0; nt < 4; nt++) {
            int col = n0 + nw + nt * 8 + 2 * (lane & 3);
            if (col < N) {
                if (H16OUT == 0) {
                    float2 v0 = make_float2(acc[mt][nt][0], acc[mt][nt][1]);
                    float2 v1 = make_float2(acc[mt][nt][2], acc[mt][nt][3]);
                    *(float2*)(C + (size_t)r0 * ldc + col) = v0;
                    *(float2*)(C + (size_t)(r0 + 8) * ldc + col) = v1;
                } else {
                    *(uint32_t*)(Ch + (size_t)r0 * ldc + col) =
                        packh(acc[mt][nt][0], acc[mt][nt][1]);
                    *(uint32_t*)(Ch + (size_t)(r0 + 8) * ldc + col) =
                        packh(acc[mt][nt][2], acc[mt][nt][3]);
                }
            }
        }
    }
}

// single fp32-out GEMM (out-proj)
__global__ void __launch_bounds__(256, 2) gemm1_k(
    const h16* __restrict__ A, const h16* __restrict__ B, float* __restrict__ C,
    int N, int K, int lda, int ldb, int ldc)
{
    extern __shared__ char smem[];
    gemm_body<0>(A, B, C, nullptr, N, K, lda, ldb, ldc,
                 blockIdx.y * 128, blockIdx.x * 128, smem);
}

// dual fp32-out GEMM (down-proj: q-low + kv)
__global__ void __launch_bounds__(256, 2) gemm1_dual_k(
    const h16* __restrict__ A0, const h16* __restrict__ B0, float* __restrict__ C0,
    int N0, int K0, int lda0, int ldb0, int ldc0,
    const h16* __restrict__ A1, const h16* __restrict__ B1, float* __restrict__ C1,
    int N1, int K1, int lda1, int ldb1, int ldc1, int nx0)
{
    extern __shared__ char smem[];
    if ((int)blockIdx.x < nx0)
        gemm_body<0>(A0, B0, C0, nullptr, N0, K0, lda0, ldb0, ldc0,
                     blockIdx.y * 128, blockIdx.x * 128, smem);
    else
        gemm_body<0>(A1, B1, C1, nullptr, N1, K1, lda1, ldb1, ldc1,
                     blockIdx.y * 128, (blockIdx.x - nx0) * 128, smem);
}

// dual fp16-out GEMM (q up-proj + kv up-proj)
__global__ void __launch_bounds__(256, 2) gemm1h_dual_k(
    const h16* __restrict__ A0, const h16* __restrict__ B0, h16* __restrict__ C0,
    int N0, int K0, int lda0, int ldb0, int ldc0,
    const h16* __restrict__ A1, const h16* __restrict__ B1, h16* __restrict__ C1,
    int N1, int K1, int lda1, int ldb1, int ldc1, int nx0)
{
    extern __shared__ char smem[];
    if ((int)blockIdx.x < nx0)
        gemm_body<1>(A0, B0, nullptr, C0, N0, K0, lda0, ldb0, ldc0,
                     blockIdx.y * 128, blockIdx.x * 128, smem);
    else
        gemm_body<1>(A1, B1, nullptr, C1, N1, K1, lda1, ldb1, ldc1,
                     blockIdx.y * 128, (blockIdx.x - nx0) * 128, smem);
}

// ---------------------------------------------------------------------------
// Fused flash attention, single fp16 planes. 112KB smem -> 2 CTAs/SM.
// (unchanged from R15)
// ---------------------------------------------------------------------------
#define FL_SMEM 114688
__global__ void __launch_bounds__(256, 2) flash_k(
    const h16* __restrict__ q_, const h16* __restrict__ kv_,
    const h16* __restrict__ kpe_,
    const float* __restrict__ mb, const int* __restrict__ pos,
    h16* __restrict__ at_)
{
    extern __shared__ char smem[];
    int bh = blockIdx.x, b = bh >> 5, h = bh & 31;
    int qi = 7 - blockIdx.y;
    int t0 = qi * 128;
    int tid = threadIdx.x, lane = tid & 31, wid = tid >> 5;
    int wrow = wid * 16;

    uint32_t S0 = smem_u32(smem);
    uint32_t Qs = S0;                  // 49152
    uint32_t Kb = S0 + 49152;          // 2 stages x 24576
    uint32_t Vb = S0 + 98304;          // 16384

    const h16* Qg = q_ + ((size_t)(b * 1024 + t0)) * 6144 + h * 192;
    const h16* KN = kv_ + (size_t)b * 1024 * 8192 + h * 256;
    const h16* KP = kpe_ + (size_t)b * 1024 * 64;
    const h16* Vg = KN + 128;
    const float* mbb = mb + b * 1024;

#pragma unroll
    for (int sp = 0; sp < 6; sp++)
        load_plane(Qs + sp * 8192, Qg, 0, 6144, sp * 32, tid, 128);
#pragma unroll
    for (int sp = 0; sp < 4; sp++)
        load_plane64(Kb + sp * 4096, KN + sp * 32, 8192, tid);
#pragma unroll
    for (int sp = 4; sp < 6; sp++)
        load_plane64(Kb + sp * 4096, KP + (sp - 4) * 32, 64, tid);
    CP_COMMIT();

    // ---- rope Q pe columns (subplanes 4,5) in smem ----
    CP_WAIT(0);
    __syncthreads();
    {
        int j = tid & 31;
        float invf = powf(10000.f, -(float)j / 32.f);
#pragma unroll
        for (int it = 0; it < 16; it++) {
            int r = (tid >> 5) + it * 8;
            uint32_t off = (uint32_t)(r * 64 +
                (((j >> 3) ^ ((r >> 1) & 3)) << 4) + (j & 7) * 2);
            h16* q4 = (h16*)(smem + 4 * 8192 + off);
            h16* q5 = (h16*)(smem + 5 * 8192 + off);
            float x1 = __half2float(*q4), x2 = __half2float(*q5);
            float p = (float)pos[b * 1024 + t0 + r];
            float sn, cs; sincosf(p * invf, &sn, &cs);
            *q4 = __float2half_rn(x1 * cs - x2 * sn);
            *q5 = __float2half_rn(x1 * sn + x2 * cs);
        }
    }

    int nst = (t0 + 128) >> 6;
    float m0 = -1e30f, m1 = -1e30f, l0 = 0.f, l1 = 0.f;
    float O[16][4];
#pragma unroll
    for (int i = 0; i < 16; i++)
#pragma unroll
        for (int j = 0; j < 4; j++) O[i][j] = 0.f;

    int rA = wrow + (lane & 15);
    int swA = (rA >> 1) & 3;
    int rB[4], swB[4];
#pragma unroll
    for (int g = 0; g < 4; g++) {
        rB[g] = g * 16 + (lane & 7) + ((lane >> 4) << 3);
        swB[g] = (rB[g] >> 1) & 3;
    }
    int aSel = (lane >> 4) & 1, bSel = (lane >> 3) & 1;
    int trow = t0 + wrow + (lane >> 2);

    for (int i = 0; i < nst; i++) {
        __syncthreads();
        load_v(Vb, Vg + (size_t)i * 64 * 8192, 8192, tid);
        CP_COMMIT();
        if (i + 1 < nst) {
            uint32_t Ks = Kb + ((i + 1) & 1) * 24576;
            size_t roff = (size_t)(i + 1) * 64;
#pragma unroll
            for (int sp = 0; sp < 4; sp++)
                load_plane64(Ks + sp * 4096, KN + roff * 8192 + sp * 32, 8192, tid);
#pragma unroll
            for (int sp = 4; sp < 6; sp++)
                load_plane64(Ks + sp * 4096, KP + roff * 64 + (sp - 4) * 32, 64, tid);
        }
        CP_COMMIT();

        CP_WAIT(2);
        __syncthreads();

        // ---- S = QK^T ----
        float S[8][4];
#pragma unroll
        for (int nt = 0; nt < 8; nt++)
#pragma unroll
            for (int j = 0; j < 4; j++) S[nt][j] = 0.f;

        uint32_t Ks = Kb + (i & 1) * 24576;
#pragma unroll
        for (int ks = 0; ks < 12; ks++) {
            int sp = ks >> 1;
            int cA = ((ks & 1) << 1) + aSel;
            int cB = ((ks & 1) << 1) + bSel;
            uint32_t ah[4], bf[4][4];
            LDSM4(ah, Qs + sp * 8192 + rA * 64 + (uint32_t)((cA ^ swA) << 4));
#pragma unroll
            for (int g = 0; g < 4; g++)
                LDSM4(bf[g], Ks + sp * 4096 + rB[g] * 64 + (uint32_t)((cB ^ swB[g]) << 4));
#pragma unroll
            for (int g = 0; g < 4; g++) {
                MMAH(S[2 * g], ah, bf[g][0], bf[g][1]);
                MMAH(S[2 * g + 1], ah, bf[g][2], bf[g][3]);
            }
        }

        // ---- online softmax ----
        int s0i = i * 64;
        float mx0 = -1e30f, mx1 = -1e30f;
#pragma unroll
        for (int nt = 0; nt < 8; nt++) {
            int sb0 = s0i + nt * 8 + ((lane & 3) << 1);
            float bias0 = mbb[sb0], bias1 = mbb[sb0 + 1];
            float v0 = S[nt][0] * SCALE_QK + bias0; if (sb0     > trow)     v0 = -1e30f;
            float v1 = S[nt][1] * SCALE_QK + bias1; if (sb0 + 1 > trow)     v1 = -1e30f;
            float v2 = S[nt][2] * SCALE_QK + bias0; if (sb0     > trow + 8) v2 = -1e30f;
            float v3 = S[nt][3] * SCALE_QK + bias1; if (sb0 + 1 > trow + 8) v3 = -1e30f;
            S[nt][0] = v0; S[nt][1] = v1; S[nt][2] = v2; S[nt][3] = v3;
            mx0 = fmaxf(mx0, fmaxf(v0, v1));
            mx1 = fmaxf(mx1, fmaxf(v2, v3));
        }
        mx0 = fmaxf(mx0, __shfl_xor_sync(0xffffffffu, mx0, 1));
        mx0 = fmaxf(mx0, __shfl_xor_sync(0xffffffffu, mx0, 2));
        mx1 = fmaxf(mx1, __shfl_xor_sync(0xffffffffu, mx1, 1));
        mx1 = fmaxf(mx1, __shfl_xor_sync(0xffffffffu, mx1, 2));
        float mn0 = fmaxf(m0, mx0), mn1 = fmaxf(m1, mx1);
        float cr0 = __expf(m0 - mn0), cr1 = __expf(m1 - mn1);
        float sum0 = 0.f, sum1 = 0.f;
#pragma unroll
        for (int nt = 0; nt < 8; nt++) {
            S[nt][0] = __expf(S[nt][0] - mn0);
            S[nt][1] = __expf(S[nt][1] - mn0);
            S[nt][2] = __expf(S[nt][2] - mn1);
            S[nt][3] = __expf(S[nt][3] - mn1);
            sum0 += S[nt][0] + S[nt][1];
            sum1 += S[nt][2] + S[nt][3];
        }
        sum0 += __shfl_xor_sync(0xffffffffu, sum0, 1);
        sum0 += __shfl_xor_sync(0xffffffffu, sum0, 2);
        sum1 += __shfl_xor_sync(0xffffffffu, sum1, 1);
        sum1 += __shfl_xor_sync(0xffffffffu, sum1, 2);
        l0 = l0 * cr0 + sum0;  l1 = l1 * cr1 + sum1;
        m0 = mn0;  m1 = mn1;
#pragma unroll
        for (int nd = 0; nd < 16; nd++) {
            O[nd][0] *= cr0; O[nd][1] *= cr0;
            O[nd][2] *= cr1; O[nd][3] *= cr1;
        }

        CP_WAIT(1);
        __syncthreads();

        // ---- O += P @ V ----
        int rV = (lane & 15);
#pragma unroll
        for (int kc = 0; kc < 4; kc++) {
            uint32_t phi[4];
#pragma unroll
            for (int j = 0; j < 2; j++) {
                int nt = 2 * kc + j;
                phi[2 * j]     = packh(S[nt][0], S[nt][1]);
                phi[2 * j + 1] = packh(S[nt][2], S[nt][3]);
            }
            int row = kc * 16 + rV;
            int sw = row & 7;
            uint32_t rbase = (uint32_t)row * 256;
            int cgrp = (lane >> 4) << 3;
#pragma unroll
            for (int g = 0; g < 8; g++) {
                int cch = (((g << 4) + cgrp) >> 3) ^ sw;
                uint32_t v4[4];
                LDSM4T(v4, Vb + rbase + (uint32_t)(cch << 4));
                MMAH_P(O[2 * g],     phi[0], phi[1], phi[2], phi[3], v4[0], v4[1]);
                MMAH_P(O[2 * g + 1], phi[0], phi[1], phi[2], phi[3], v4[2], v4[3]);
            }
        }
    }

    // ---- epilogue: O / l -> fp16 plane ----
    float inv0 = 1.f / l0, inv1 = 1.f / l1;
    size_t row0 = ((size_t)(b * 1024) + trow) * 4096 + h * 128;
    size_t row1 = row0 + (size_t)8 * 4096;
    int dcol = (lane & 3) * 2;
#pragma unroll
    for (int nd = 0; nd < 16; nd++) {
        int c = nd * 8 + dcol;
        *(uint32_t*)(at_ + row0 + c) = packh(O[nd][0] * inv0, O[nd][1] * inv0);
        *(uint32_t*)(at_ + row1 + c) = packh(O[nd][2] * inv1, O[nd][3] * inv1);
    }
}

// ------------------------- conversion / elementwise -------------------------
// Flat vectorized fp32->fp16 convert for all weights + x (no transpose).
// Segment block counts (1024 elems each): wq_a 6144 | wkv_a 2304 | wq_b 9216 |
// wkv_b 4096 | wo 16384 | x 8192  => 46336 blocks total.
__global__ void prep_k(const float* __restrict__ wq_a,
                       const float* __restrict__ wkv_a,
                       const float* __restrict__ wq_b,
                       const float* __restrict__ wkv_b,
                       const float* __restrict__ wo,
                       const float* __restrict__ x,
                       h16* __restrict__ wqa, h16* __restrict__ wkva,
                       h16* __restrict__ wqb, h16* __restrict__ wkvb,
                       h16* __restrict__ wot, h16* __restrict__ xh)
{
    int bx = blockIdx.x;
    const float* S; h16* D; long off;
    if (bx < 6144)       { S = wq_a;  D = wqa;  off = (long)bx * 1024; }
    else if (bx < 8448)  { S = wkv_a; D = wkva; off = (long)(bx - 6144) * 1024; }
    else if (bx < 17664) { S = wq_b;  D = wqb;  off = (long)(bx - 8448) * 1024; }
    else if (bx < 21760) { S = wkv_b; D = wkvb; off = (long)(bx - 17664) * 1024; }
    else if (bx < 38144) { S = wo;    D = wot;  off = (long)(bx - 21760) * 1024; }
    else                 { S = x;     D = xh;   off = (long)(bx - 38144) * 1024; }
    long i = off + threadIdx.x * 4;
    float4 v = *(const float4*)(S + i);
    *(uint2*)(D + i) = make_uint2(packh(v.x, v.y), packh(v.z, v.w));
}

// Fused post-down-proj: rmsnorms -> fp16, rope k_pe -> plane, mask bias.
__global__ void postdown_k(const float* __restrict__ qkv,
                           const float* __restrict__ qw,
                           const float* __restrict__ kvw,
                           const int* __restrict__ amask,
                           const int* __restrict__ pos,
                           h16* __restrict__ qlow, h16* __restrict__ kv,
                           h16* __restrict__ kpe, float* __restrict__ mb)
{
    int rb = blockIdx.x;
    int tid = threadIdx.x;
    if (rb >= 4352) {                       // mask bias: 8 blocks
        int i = (rb - 4352) * 256 + tid;
        if (i < 2048) mb[i] = amask[i] ? 0.f : -1e30f;
        return;
    }
    if (rb >= 4096) {                       // rope k_pe: 256 blocks x 8 warps
        int w = (rb - 4096) * 8 + (tid >> 5);
        int lane = tid & 31;
        const float* base = qkv + (size_t)w * 2112 + 2048;
        float p = (float)pos[w];
        float invf = powf(10000.f, -(float)lane / 32.f);
        float sn, cs; sincosf(p * invf, &sn, &cs);
        float x1 = base[lane], x2 = base[32 + lane];
        size_t ob = (size_t)w * 64;
        kpe[ob + lane]      = __float2half_rn(x1 * cs - x2 * sn);
        kpe[ob + 32 + lane] = __float2half_rn(x1 * sn + x2 * cs);
        return;
    }
    __shared__ float red[256];
    int isq = rb < 2048;
    long row = isq ? rb : rb - 2048;
    int n = isq ? 1536 : 512;
    const float* p = qkv + row * 2112 + (isq ? 0 : 1536);
    const float* w = isq ? qw : kvw;
    h16* oh = (isq ? qlow : kv) + row * n;
    float ss = 0.f;
    for (int c = tid; c < n; c += 256) { float v = p[c]; ss += v * v; }
    red[tid] = ss; __syncthreads();
    for (int s = 128; s > 0; s >>= 1) {
        if (tid < s) red[tid] += red[tid + s];
        __syncthreads();
    }
    float r = rsqrtf(red[0] / (float)n + 1e-6f);
    for (int c = tid; c < n; c += 256)
        oh[c] = __float2half_rn(p[c] * r * w[c]);
}

// ---------------------------------------------------------------------------
extern "C" void kernel_launch(void* const* d_in, const int* in_sizes, int n_in,
                              void* d_out, int out_size)
{
    const float* x        = (const float*)d_in[0];
    const float* wq_a     = (const float*)d_in[1];
    const float* q_norm_w = (const float*)d_in[2];
    const float* wq_b     = (const float*)d_in[3];
    const float* wkv_a    = (const float*)d_in[4];
    const float* kv_norm_w= (const float*)d_in[5];
    const float* wkv_b    = (const float*)d_in[6];
    const float* wo       = (const float*)d_in[7];
    const int*   amask    = (const int*)d_in[8];
    const int*   pos      = (const int*)d_in[9];
    float*       out      = (float*)d_out;

    cudaFuncSetAttribute(gemm1_k, cudaFuncAttributeMaxDynamicSharedMemorySize,
                         GEMM_SMEM);
    cudaFuncSetAttribute(gemm1_dual_k, cudaFuncAttributeMaxDynamicSharedMemorySize,
                         GEMM_SMEM);
    cudaFuncSetAttribute(gemm1h_dual_k, cudaFuncAttributeMaxDynamicSharedMemorySize,
                         GEMM_SMEM);
    cudaFuncSetAttribute(flash_k, cudaFuncAttributeMaxDynamicSharedMemorySize,
                         FL_SMEM);

    float *qkv, *mb;
    h16 *xh,*qlow,*q,*kv,*kvexp,*kpe,*at;
    h16 *wqa,*wkva,*wqb,*wkvb,*wot;
    cudaGetSymbolAddress((void**)&qkv,  g_qkv);
    cudaGetSymbolAddress((void**)&mb,   g_mb);
    cudaGetSymbolAddress((void**)&xh,   g_xh);
    cudaGetSymbolAddress((void**)&qlow, g_qlow);
    cudaGetSymbolAddress((void**)&q,    g_q);
    cudaGetSymbolAddress((void**)&kv,   g_kv);
    cudaGetSymbolAddress((void**)&kvexp,g_kvexp);
    cudaGetSymbolAddress((void**)&kpe,  g_kpe);
    cudaGetSymbolAddress((void**)&at,   g_at);
    cudaGetSymbolAddress((void**)&wqa,  g_wqa);
    cudaGetSymbolAddress((void**)&wkva, g_wkva);
    cudaGetSymbolAddress((void**)&wqb,  g_wqb);
    cudaGetSymbolAddress((void**)&wkvb, g_wkvb);
    cudaGetSymbolAddress((void**)&wot,  g_wo);

    // 0. flat convert (no transpose): weights + x
    prep_k<<<46336, 256>>>(wq_a, wkv_a, wq_b, wkv_b, wo, x,
                           wqa, wkva, wqb, wkvb, wot, xh);
    // 1. dual down-proj: qkv[:, :1536] = x @ wq_a ; qkv[:, 1536:2112] = x @ wkv_a
    gemm1_dual_k<<<dim3(17, 16), 256, GEMM_SMEM>>>(
        xh, wqa,  qkv,        1536, 4096, 4096, 1536, 2112,
        xh, wkva, qkv + 1536, 576,  4096, 4096, 576,  2112, 12);
    // 2. fused rmsnorms + rope k_pe + mask bias
    postdown_k<<<4360, 256>>>(qkv, q_norm_w, kv_norm_w, amask, pos,
                              qlow, kv, kpe, mb);
    // 3. dual up-proj -> fp16 planes
    gemm1h_dual_k<<<dim3(112, 16), 256, GEMM_SMEM>>>(
        qlow, wqb, q,      6144, 1536, 1536, 6144, 6144,
        kv,   wkvb, kvexp, 8192, 512, 512, 8192, 8192, 48);
    // 4. fused attention (rope-on-load, strided K/V) -> at
    flash_k<<<dim3(64, 8), 256, FL_SMEM>>>(q, kvexp, kpe, mb, pos, at);
    // 5. out = attn @ wo
    gemm1_k<<<dim3(32, 16), 256, GEMM_SMEM>>>(at, wot, out,
        4096, 4096, 4096, 4096, 4096);
}